// round 2
// baseline (speedup 1.0000x reference)
#include <cuda_runtime.h>
#include <math.h>
#include <stdint.h>

#define B_    8
#define CIN_  128
#define N_    2048
#define K_    16
#define G_    4
#define L_    192
#define NL_   64
#define CL_   48
#define CNL_  16
#define COUT_ 256
#define TILE_N 8
#define TN2   16

// ---------------- tf32 rounding (emulate cuBLAS TF32 operand conversion) ----------------
__device__ __forceinline__ float tf32r(float a) {
    uint32_t u;
    asm("cvt.rna.tf32.f32 %0, %1;" : "=r"(u) : "f"(a));
    return __uint_as_float(u);
}

// ---------------- scratch (device globals; no allocation allowed) ----------------
__device__ float g_cent[B_ * G_ * N_];
__device__ float g_vals[B_ * G_ * K_];
__device__ int   g_inds[B_ * G_ * K_];
__device__ float g_M[B_ * G_ * CNL_ * K_];
__device__ float g_nv2j[B_ * G_ * CNL_ * K_];
__device__ float g_tanhvals[B_ * G_ * K_];

// pre-rounded (tf32) weights
__device__ float r_Wq[L_ * 64];
__device__ float r_Wk[L_ * 64];
__device__ float r_Wv[L_ * CIN_];
__device__ float r_pe_w1[3 * L_];
__device__ float r_pe_w2[L_ * L_];
__device__ float r_Wnq[NL_ * 64];
__device__ float r_Wnk[NL_ * 64];
__device__ float r_Wnv1[NL_ * 64];
__device__ float r_Wnv2[NL_ * 64];
__device__ float r_npe_w1[G_ * 3 * CNL_];
__device__ float r_npe_w2[G_ * CNL_ * CNL_];

// ---------------- kernel: round weights + zero cent ----------------
__global__ void k_prep(const float* __restrict__ Wq, const float* __restrict__ Wk,
                       const float* __restrict__ Wv,
                       const float* __restrict__ pe_w1, const float* __restrict__ pe_w2,
                       const float* __restrict__ Wnq, const float* __restrict__ Wnk,
                       const float* __restrict__ Wnv1, const float* __restrict__ Wnv2,
                       const float* __restrict__ npe_w1, const float* __restrict__ npe_w2) {
    int tid = blockIdx.x * blockDim.x + threadIdx.x;
    int nth = gridDim.x * blockDim.x;
    for (int i = tid; i < L_ * 64; i += nth)   r_Wq[i] = tf32r(Wq[i]);
    for (int i = tid; i < L_ * 64; i += nth)   r_Wk[i] = tf32r(Wk[i]);
    for (int i = tid; i < L_ * CIN_; i += nth) r_Wv[i] = tf32r(Wv[i]);
    for (int i = tid; i < 3 * L_; i += nth)    r_pe_w1[i] = tf32r(pe_w1[i]);
    for (int i = tid; i < L_ * L_; i += nth)   r_pe_w2[i] = tf32r(pe_w2[i]);
    for (int i = tid; i < NL_ * 64; i += nth)  r_Wnq[i]  = tf32r(Wnq[i]);
    for (int i = tid; i < NL_ * 64; i += nth)  r_Wnk[i]  = tf32r(Wnk[i]);
    for (int i = tid; i < NL_ * 64; i += nth)  r_Wnv1[i] = tf32r(Wnv1[i]);
    for (int i = tid; i < NL_ * 64; i += nth)  r_Wnv2[i] = tf32r(Wnv2[i]);
    for (int i = tid; i < G_ * 3 * CNL_; i += nth)    r_npe_w1[i] = tf32r(npe_w1[i]);
    for (int i = tid; i < G_ * CNL_ * CNL_; i += nth) r_npe_w2[i] = tf32r(npe_w2[i]);
    for (int i = tid; i < B_ * G_ * N_; i += nth) g_cent[i] = 0.f;
}

// ---------------- kernel 1: fused local branch ----------------
__global__ __launch_bounds__(L_) void k_local(
    const float* __restrict__ x,       // (B,CIN,N,K)
    const float* __restrict__ abs_x,   // (B,64,N,1)
    const float* __restrict__ points,  // (B,3,N)
    const float* __restrict__ pe_b1,
    const float* __restrict__ pe_b2,
    const int*   __restrict__ idx,     // (B,1,N,K)
    float*       __restrict__ out)     // (B,256,N,1)
{
    const int blk = blockIdx.x;
    const int b   = blk / (N_ / TILE_N);
    const int n0  = (blk % (N_ / TILE_N)) * TILE_N;
    const int o   = threadIdx.x;   // 0..191

    __shared__ float x_s[CIN_][K_];
    __shared__ float xs_s[64][K_];
    __shared__ float absx_s[64];
    __shared__ float h_s[L_][K_];
    __shared__ float prod_s[L_][K_];
    __shared__ float rel_s[3][K_];
    __shared__ float score_s[G_][K_];
    __shared__ float att_s[G_][K_];
    __shared__ int   idx_s[K_];

    const float b1 = pe_b1[o];
    const float b2 = pe_b2[o];
    const float w1_0 = r_pe_w1[o];
    const float w1_1 = r_pe_w1[L_ + o];
    const float w1_2 = r_pe_w1[2 * L_ + o];
    const int gq = o / CL_;

    for (int nt = 0; nt < TILE_N; nt++) {
        const int n = n0 + nt;

        // ---- phase A: loads (x raw; absx rounded) ----
        const float* xb = x + ((size_t)(b * CIN_) * N_ + n) * K_;
        for (int i = o; i < CIN_ * K_; i += L_) {
            int c = i >> 4, k = i & 15;
            x_s[c][k] = xb[(size_t)c * N_ * K_ + k];
        }
        if (o < 64) absx_s[o] = tf32r(abs_x[(b * 64 + o) * N_ + n]);
        if (o < K_) idx_s[o]  = idx[(b * N_ + n) * K_ + o];
        __syncthreads();

        // ---- phase B: xs = tf32(x_lo + x_hi), rel = tf32(p-p0), lq ----
        if (o < 64) {
            #pragma unroll
            for (int k = 0; k < K_; k++) xs_s[o][k] = tf32r(x_s[o][k] + x_s[o + 64][k]);
        }
        if (o >= 64 && o < 64 + 3 * K_) {
            int t = o - 64; int c = t / K_, k = t % K_;
            float p  = points[(b * 3 + c) * N_ + idx_s[k]];
            float p0 = points[(b * 3 + c) * N_ + idx_s[0]];
            rel_s[c][k] = tf32r(p - p0);
        }
        float lq = 0.f;
        #pragma unroll 8
        for (int c = 0; c < 64; c++) lq += r_Wq[o * 64 + c] * absx_s[c];
        __syncthreads();

        // ---- phase B2: round x_s in place (operand for lv dot) ----
        for (int i = o; i < CIN_ * K_; i += L_) {
            int c = i >> 4, k = i & 15;
            x_s[c][k] = tf32r(x_s[c][k]);
        }
        __syncthreads();

        // ---- phase C: h (rounded store), lk accum, lv ----
        #pragma unroll
        for (int k = 0; k < K_; k++) {
            float hv = rel_s[0][k] * w1_0 + rel_s[1][k] * w1_1 + rel_s[2][k] * w1_2 + b1;
            h_s[o][k] = tf32r(hv > 0.f ? hv : 0.f);
        }
        float acc[K_];
        #pragma unroll
        for (int k = 0; k < K_; k++) acc[k] = b2;
        #pragma unroll 4
        for (int c = 0; c < 64; c++) {
            float w = r_Wk[o * 64 + c];
            #pragma unroll
            for (int k = 0; k < K_; k++) acc[k] += w * xs_s[c][k];
        }
        float lv[K_];
        #pragma unroll
        for (int k = 0; k < K_; k++) lv[k] = 0.f;
        #pragma unroll 4
        for (int c = 0; c < CIN_; c++) {
            float w = r_Wv[o * CIN_ + c];
            #pragma unroll
            for (int k = 0; k < K_; k++) lv[k] += w * x_s[c][k];
        }
        __syncthreads();   // h_s ready

        // ---- phase D: pe accumulate + prod (fp32) ----
        #pragma unroll 4
        for (int d = 0; d < L_; d++) {
            float w = r_pe_w2[d * L_ + o];
            #pragma unroll
            for (int k = 0; k < K_; k++) acc[k] += w * h_s[d][k];
        }
        #pragma unroll
        for (int k = 0; k < K_; k++) prod_s[o][k] = lq * acc[k];
        __syncthreads();

        // ---- phase E: group score reduction (fp32) ----
        if (o < G_ * K_) {
            int g = o >> 4, k = o & 15;
            float s = 0.f;
            #pragma unroll 8
            for (int c = 0; c < CL_; c++) s += prod_s[g * CL_ + c][k];
            score_s[g][k] = s;
        }
        __syncthreads();

        // ---- phase F: softmax per group (fp32) ----
        if (o < G_) {
            float m = -1e30f;
            #pragma unroll
            for (int k = 0; k < K_; k++) m = fmaxf(m, score_s[o][k]);
            float sum = 0.f;
            float e[K_];
            #pragma unroll
            for (int k = 0; k < K_; k++) { e[k] = expf(score_s[o][k] - m); sum += e[k]; }
            float inv = 1.f / sum;
            #pragma unroll
            for (int k = 0; k < K_; k++) att_s[o][k] = e[k] * inv;
        }
        __syncthreads();

        // ---- phase G: scatter (raw att) + output (tf32 dot att·lv) ----
        if (o < G_ * K_) {
            int g = o >> 4, k = o & 15;
            atomicAdd(&g_cent[(b * G_ + g) * N_ + idx_s[k]], att_s[g][k]);
        }
        float og = 0.f;
        #pragma unroll
        for (int k = 0; k < K_; k++) og += tf32r(att_s[gq][k]) * tf32r(lv[k]);
        out[((size_t)b * COUT_ + o) * N_ + n] = og;
        __syncthreads();
    }
}

// ---------------- kernel 2: top-16 per (b,g), desc, tie -> lower index ----------------
__global__ __launch_bounds__(256) void k_topk() {
    const int bg  = blockIdx.x;
    const int tid = threadIdx.x;
    __shared__ float v_s[N_];
    __shared__ float rv[256];
    __shared__ int   ri[256];

    for (int i = tid; i < N_; i += 256) v_s[i] = g_cent[bg * N_ + i];
    __syncthreads();

    for (int t = 0; t < K_; t++) {
        float bv = -1e30f; int bi = N_;
        for (int i = tid; i < N_; i += 256) {
            float v = v_s[i];
            if (v > bv || (v == bv && i < bi)) { bv = v; bi = i; }
        }
        rv[tid] = bv; ri[tid] = bi;
        __syncthreads();
        for (int s = 128; s > 0; s >>= 1) {
            if (tid < s) {
                if (rv[tid + s] > rv[tid] ||
                    (rv[tid + s] == rv[tid] && ri[tid + s] < ri[tid])) {
                    rv[tid] = rv[tid + s]; ri[tid] = ri[tid + s];
                }
            }
            __syncthreads();
        }
        if (tid == 0) {
            g_vals[bg * K_ + t] = rv[0];
            g_inds[bg * K_ + t] = ri[0];
            v_s[ri[0]] = -1e30f;
        }
        __syncthreads();
    }
}

// ---------------- kernel 3: non-local prep per (b,g) ----------------
__global__ __launch_bounds__(256) void k_nl_prep(
    const float* __restrict__ abs_x,
    const float* __restrict__ points,
    const float* __restrict__ npe_b1,
    const float* __restrict__ npe_b2)
{
    const int bg = blockIdx.x;
    const int b = bg / G_, g = bg % G_;
    const int tid = threadIdx.x;

    __shared__ int   inds_s[K_];
    __shared__ float rel_s[3][K_];
    __shared__ float h2_s[K_][CNL_];

    if (tid < K_) {
        inds_s[tid] = g_inds[bg * K_ + tid];
        g_tanhvals[bg * K_ + tid] = tanhf(g_vals[bg * K_ + tid]);
    }
    __syncthreads();
    if (tid < 3 * K_) {
        int c = tid / K_, j = tid % K_;
        rel_s[c][j] = tf32r(points[(b * 3 + c) * N_ + inds_s[j]]
                          - points[(b * 3 + c) * N_ + inds_s[0]]);
    }
    __syncthreads();
    {   // h2 (tf32 dot, K=3), rounded store
        int j = tid / CNL_, d = tid % CNL_;
        float h = npe_b1[g * CNL_ + d];
        #pragma unroll
        for (int c = 0; c < 3; c++) h += rel_s[c][j] * r_npe_w1[(g * 3 + c) * CNL_ + d];
        h2_s[j][d] = tf32r(h > 0.f ? h : 0.f);
    }
    __syncthreads();
    {   // pe_nl + gathered nk/nv2 (tf32 dots)
        int c = tid / K_, j = tid % K_;
        float pe = npe_b2[g * CNL_ + c];
        #pragma unroll
        for (int d = 0; d < CNL_; d++) pe += h2_s[j][d] * r_npe_w2[(g * CNL_ + d) * CNL_ + c];
        int nn = inds_s[j];
        float nk = 0.f, nv2 = 0.f;
        const int row = (g * CNL_ + c) * 64;
        #pragma unroll 8
        for (int cc = 0; cc < 64; cc++) {
            float a = tf32r(abs_x[(b * 64 + cc) * N_ + nn]);
            nk  += r_Wnk[row + cc]  * a;
            nv2 += r_Wnv2[row + cc] * a;
        }
        g_M[bg * CNL_ * K_ + c * K_ + j]    = nk + pe;   // raw; rounded at next dot
        g_nv2j[bg * CNL_ * K_ + c * K_ + j] = nv2;
    }
}

// ---------------- kernel 4: non-local main, per (b,n) ----------------
__global__ __launch_bounds__(64) void k_nl_main(
    const float* __restrict__ abs_x,
    float*       __restrict__ out)
{
    const int blk = blockIdx.x;
    const int b   = blk / (N_ / TN2);
    const int n0  = (blk % (N_ / TN2)) * TN2;
    const int tid = threadIdx.x;       // 0..63
    const int g = tid / CNL_, c = tid % CNL_;

    __shared__ float M_s[G_ * CNL_ * K_];
    __shared__ float nv2j_s[G_ * CNL_ * K_];
    __shared__ float tv_s[G_ * K_];
    __shared__ float a2_s[64];
    __shared__ float nq_s[G_][CNL_];
    __shared__ float score_s[G_][K_];
    __shared__ float w_s[G_][K_];
    __shared__ float ssum_s[G_];

    for (int i = tid; i < G_ * CNL_ * K_; i += 64) {
        M_s[i]    = tf32r(g_M[b * G_ * CNL_ * K_ + i]);
        nv2j_s[i] = tf32r(g_nv2j[b * G_ * CNL_ * K_ + i]);
    }
    if (tid < G_ * K_) tv_s[tid] = g_tanhvals[b * G_ * K_ + tid];
    __syncthreads();

    for (int nt = 0; nt < TN2; nt++) {
        const int n = n0 + nt;
        a2_s[tid] = tf32r(abs_x[(b * 64 + tid) * N_ + n]);
        __syncthreads();

        float nq = 0.f, nv1 = 0.f, nv2 = 0.f;
        const int row = tid * 64;
        #pragma unroll 8
        for (int cc = 0; cc < 64; cc++) {
            float a = a2_s[cc];
            nq  += r_Wnq[row + cc]  * a;
            nv1 += r_Wnv1[row + cc] * a;
            nv2 += r_Wnv2[row + cc] * a;
        }
        nq_s[g][c] = tf32r(nq);
        __syncthreads();

        {   // score (tf32 dot)
            float sc = 0.f;
            #pragma unroll
            for (int c2 = 0; c2 < CNL_; c2++)
                sc += nq_s[g][c2] * M_s[g * CNL_ * K_ + c2 * K_ + c];
            score_s[g][c] = sc;
        }
        __syncthreads();
        if (c == 0) {
            float m = -1e30f;
            #pragma unroll
            for (int j = 0; j < K_; j++) m = fmaxf(m, score_s[g][j]);
            float sum = 0.f; float e[K_];
            #pragma unroll
            for (int j = 0; j < K_; j++) { e[j] = expf(score_s[g][j] - m); sum += e[j]; }
            float inv = 1.f / sum;
            float ws = 0.f;
            #pragma unroll
            for (int j = 0; j < K_; j++) {
                float w = e[j] * inv * tv_s[g * K_ + j];
                w_s[g][j] = w; ws += w;
            }
            ssum_s[g] = ws;
        }
        __syncthreads();

        // output: (nv1-nv2)*s elementwise fp32 + tf32 dot w·nv2j
        float og = (nv1 - nv2) * ssum_s[g];
        #pragma unroll
        for (int j = 0; j < K_; j++)
            og += tf32r(w_s[g][j]) * nv2j_s[g * CNL_ * K_ + c * K_ + j];
        out[((size_t)b * COUT_ + L_ + tid) * N_ + n] = og;
        __syncthreads();
    }
}

// ---------------- launcher ----------------
extern "C" void kernel_launch(void* const* d_in, const int* in_sizes, int n_in,
                              void* d_out, int out_size) {
    const float* x      = (const float*)d_in[0];
    const float* abs_x  = (const float*)d_in[1];
    const float* points = (const float*)d_in[2];
    const float* Wq     = (const float*)d_in[3];
    const float* Wk     = (const float*)d_in[4];
    const float* Wv     = (const float*)d_in[5];
    const float* Wnq    = (const float*)d_in[6];
    const float* Wnk    = (const float*)d_in[7];
    const float* Wnv1   = (const float*)d_in[8];
    const float* Wnv2   = (const float*)d_in[9];
    const float* pe_w1  = (const float*)d_in[10];
    const float* pe_b1  = (const float*)d_in[11];
    const float* pe_w2  = (const float*)d_in[12];
    const float* pe_b2  = (const float*)d_in[13];
    const float* npe_w1 = (const float*)d_in[14];
    const float* npe_b1 = (const float*)d_in[15];
    const float* npe_w2 = (const float*)d_in[16];
    const float* npe_b2 = (const float*)d_in[17];
    const int*   idx    = (const int*)d_in[18];
    float* out = (float*)d_out;

    k_prep<<<128, 256>>>(Wq, Wk, Wv, pe_w1, pe_w2, Wnq, Wnk, Wnv1, Wnv2, npe_w1, npe_w2);
    k_local<<<B_ * (N_ / TILE_N), L_>>>(x, abs_x, points, pe_b1, pe_b2, idx, out);
    k_topk<<<B_ * G_, 256>>>();
    k_nl_prep<<<B_ * G_, 256>>>(abs_x, points, npe_b1, npe_b2);
    k_nl_main<<<B_ * (N_ / TN2), 64>>>(abs_x, out);
}

// round 3
// speedup vs baseline: 2.5474x; 2.5474x over previous
#include <cuda_runtime.h>
#include <math.h>
#include <stdint.h>

#define B_    8
#define CIN_  128
#define N_    2048
#define K_    16
#define G_    4
#define L_    192
#define NL_   64
#define CL_   48
#define CNL_  16
#define COUT_ 256
#define TILE_N 8
#define NB    2
#define TN2   16

// ---------------- tf32 rounding (emulate cuBLAS TF32 operand conversion) ----------------
__device__ __forceinline__ float tf32r(float a) {
    uint32_t u;
    asm("cvt.rna.tf32.f32 %0, %1;" : "=r"(u) : "f"(a));
    return __uint_as_float(u);
}

// ---------------- scratch (device globals) ----------------
__device__ float g_cent[B_ * G_ * N_];
__device__ float g_vals[B_ * G_ * K_];
__device__ int   g_inds[B_ * G_ * K_];
__device__ float g_M[B_ * G_ * CNL_ * K_];
__device__ float g_nv2j[B_ * G_ * CNL_ * K_];
__device__ float g_tanhvals[B_ * G_ * K_];

// pre-rounded (tf32) weights; T suffix = transposed to [c][o] for coalesced reads
__device__ float rT_Wq[64 * L_];
__device__ float rT_Wk[64 * L_];
__device__ float rT_Wv[CIN_ * L_];
__device__ float r_pe_w1[3 * L_];
__device__ float r_pe_w2[L_ * L_];          // already [d][e] -> coalesced in o
__device__ float rT_Wnq[64 * NL_];
__device__ float rT_Wnk[64 * NL_];
__device__ float rT_Wnv1[64 * NL_];
__device__ float rT_Wnv2[64 * NL_];
__device__ float r_npe_w1[G_ * 3 * CNL_];
__device__ float r_npe_w2[G_ * CNL_ * CNL_];

// ---------------- kernel: round + transpose weights, zero cent ----------------
__global__ void k_prep(const float* __restrict__ Wq, const float* __restrict__ Wk,
                       const float* __restrict__ Wv,
                       const float* __restrict__ pe_w1, const float* __restrict__ pe_w2,
                       const float* __restrict__ Wnq, const float* __restrict__ Wnk,
                       const float* __restrict__ Wnv1, const float* __restrict__ Wnv2,
                       const float* __restrict__ npe_w1, const float* __restrict__ npe_w2) {
    int tid = blockIdx.x * blockDim.x + threadIdx.x;
    int nth = gridDim.x * blockDim.x;
    for (int i = tid; i < 64 * L_; i += nth) {
        int c = i / L_, o = i % L_;
        rT_Wq[i] = tf32r(Wq[o * 64 + c]);
        rT_Wk[i] = tf32r(Wk[o * 64 + c]);
    }
    for (int i = tid; i < CIN_ * L_; i += nth) {
        int c = i / L_, o = i % L_;
        rT_Wv[i] = tf32r(Wv[o * CIN_ + c]);
    }
    for (int i = tid; i < 3 * L_; i += nth)  r_pe_w1[i] = tf32r(pe_w1[i]);
    for (int i = tid; i < L_ * L_; i += nth) r_pe_w2[i] = tf32r(pe_w2[i]);
    for (int i = tid; i < 64 * NL_; i += nth) {
        int c = i / NL_, o = i % NL_;
        rT_Wnq[i]  = tf32r(Wnq[o * 64 + c]);
        rT_Wnk[i]  = tf32r(Wnk[o * 64 + c]);
        rT_Wnv1[i] = tf32r(Wnv1[o * 64 + c]);
        rT_Wnv2[i] = tf32r(Wnv2[o * 64 + c]);
    }
    for (int i = tid; i < G_ * 3 * CNL_; i += nth)    r_npe_w1[i] = tf32r(npe_w1[i]);
    for (int i = tid; i < G_ * CNL_ * CNL_; i += nth) r_npe_w2[i] = tf32r(npe_w2[i]);
    for (int i = tid; i < B_ * G_ * N_; i += nth) g_cent[i] = 0.f;
}

// ---------------- kernel 1: fused local branch ----------------
struct LocalSmem {
    float x[NB][CIN_][K_];     // 16 KB : raw, then tf32-rounded in place
    float xs[NB][64][K_];      // 8 KB
    float h[NB][L_][K_];       // 24 KB : h, then reused as prod
    float outbuf[L_][TILE_N];  // 6 KB
    float absx[NB][64];
    float rel[NB][3][K_];
    float score[NB][G_][K_];
    float att[NB][G_][K_];
    int   idxs[NB][K_];
};

__global__ __launch_bounds__(L_) void k_local(
    const float* __restrict__ x,
    const float* __restrict__ abs_x,
    const float* __restrict__ points,
    const float* __restrict__ pe_b1,
    const float* __restrict__ pe_b2,
    const int*   __restrict__ idx,
    float*       __restrict__ out)
{
    extern __shared__ char smem_raw[];
    LocalSmem* s = (LocalSmem*)smem_raw;

    const int blk = blockIdx.x;
    const int b   = blk / (N_ / TILE_N);
    const int n0  = (blk % (N_ / TILE_N)) * TILE_N;
    const int o   = threadIdx.x;   // 0..191

    const float b1 = pe_b1[o];
    const float b2 = pe_b2[o];
    const float w1_0 = r_pe_w1[o];
    const float w1_1 = r_pe_w1[L_ + o];
    const float w1_2 = r_pe_w1[2 * L_ + o];
    const int gq = o / CL_;

    for (int it = 0; it < TILE_N / NB; it++) {
        const int nbase = n0 + it * NB;

        // ---- phase A: loads (x raw; absx rounded) ----
        for (int i = o; i < NB * CIN_ * K_; i += L_) {
            int v = i >> 11, r = i & 2047;
            int c = r >> 4, k = r & 15;
            s->x[v][c][k] = x[((size_t)(b * CIN_ + c) * N_ + nbase + v) * K_ + k];
        }
        if (o < 64) {
            #pragma unroll
            for (int v = 0; v < NB; v++)
                s->absx[v][o] = tf32r(abs_x[(b * 64 + o) * N_ + nbase + v]);
        }
        if (o < NB * K_) {
            int v = o >> 4, k = o & 15;
            s->idxs[v][k] = idx[(b * N_ + nbase + v) * K_ + k];
        }
        __syncthreads();

        // ---- phase B: xs = tf32(x_lo + x_hi), rel, lq ----
        if (o < 64) {
            #pragma unroll
            for (int v = 0; v < NB; v++)
                #pragma unroll
                for (int k = 0; k < K_; k++)
                    s->xs[v][o][k] = tf32r(s->x[v][o][k] + s->x[v][o + 64][k]);
        } else if (o < 64 + 3 * K_) {
            int t = o - 64; int c = t / K_, k = t % K_;
            #pragma unroll
            for (int v = 0; v < NB; v++) {
                float p  = points[(b * 3 + c) * N_ + s->idxs[v][k]];
                float p0 = points[(b * 3 + c) * N_ + s->idxs[v][0]];
                s->rel[v][c][k] = tf32r(p - p0);
            }
        }
        float lq[NB];
        #pragma unroll
        for (int v = 0; v < NB; v++) lq[v] = 0.f;
        #pragma unroll 4
        for (int c = 0; c < 64; c++) {
            float w = rT_Wq[c * L_ + o];
            #pragma unroll
            for (int v = 0; v < NB; v++) lq[v] += w * s->absx[v][c];
        }
        __syncthreads();

        // ---- phase B2: round x in place (lv operand) ----
        {
            float* xf = &s->x[0][0][0];
            for (int i = o; i < NB * CIN_ * K_; i += L_) xf[i] = tf32r(xf[i]);
        }
        __syncthreads();

        // ---- phase C: h store, lk accum, lv ----
        #pragma unroll
        for (int v = 0; v < NB; v++)
            #pragma unroll
            for (int k = 0; k < K_; k++) {
                float hv = s->rel[v][0][k] * w1_0 + s->rel[v][1][k] * w1_1
                         + s->rel[v][2][k] * w1_2 + b1;
                s->h[v][o][k] = tf32r(hv > 0.f ? hv : 0.f);
            }
        float acc[NB][K_];
        #pragma unroll
        for (int v = 0; v < NB; v++)
            #pragma unroll
            for (int k = 0; k < K_; k++) acc[v][k] = b2;
        #pragma unroll 2
        for (int c = 0; c < 64; c++) {
            float w = rT_Wk[c * L_ + o];
            #pragma unroll
            for (int v = 0; v < NB; v++)
                #pragma unroll
                for (int k = 0; k < K_; k++) acc[v][k] += w * s->xs[v][c][k];
        }
        float lv[NB][K_];
        #pragma unroll
        for (int v = 0; v < NB; v++)
            #pragma unroll
            for (int k = 0; k < K_; k++) lv[v][k] = 0.f;
        #pragma unroll 2
        for (int c = 0; c < CIN_; c++) {
            float w = rT_Wv[c * L_ + o];
            #pragma unroll
            for (int v = 0; v < NB; v++)
                #pragma unroll
                for (int k = 0; k < K_; k++) lv[v][k] += w * s->x[v][c][k];
        }
        __syncthreads();   // h ready

        // ---- phase D: pe accumulate ----
        #pragma unroll 2
        for (int d = 0; d < L_; d++) {
            float w = r_pe_w2[d * L_ + o];
            #pragma unroll
            for (int v = 0; v < NB; v++)
                #pragma unroll
                for (int k = 0; k < K_; k++) acc[v][k] += w * s->h[v][d][k];
        }
        __syncthreads();   // all h reads done; reuse as prod

        #pragma unroll
        for (int v = 0; v < NB; v++)
            #pragma unroll
            for (int k = 0; k < K_; k++) s->h[v][o][k] = lq[v] * acc[v][k];
        __syncthreads();

        // ---- phase E: group score reduction ----
        if (o < G_ * K_) {
            int g = o >> 4, k = o & 15;
            #pragma unroll
            for (int v = 0; v < NB; v++) {
                float sc = 0.f;
                #pragma unroll 8
                for (int c = 0; c < CL_; c++) sc += s->h[v][g * CL_ + c][k];
                s->score[v][g][k] = sc;
            }
        }
        __syncthreads();

        // ---- phase F: softmax per group ----
        if (o < NB * G_) {
            int v = o / G_, g = o % G_;
            float m = -1e30f;
            #pragma unroll
            for (int k = 0; k < K_; k++) m = fmaxf(m, s->score[v][g][k]);
            float sum = 0.f; float e[K_];
            #pragma unroll
            for (int k = 0; k < K_; k++) { e[k] = expf(s->score[v][g][k] - m); sum += e[k]; }
            float inv = 1.f / sum;
            #pragma unroll
            for (int k = 0; k < K_; k++) s->att[v][g][k] = e[k] * inv;
        }
        __syncthreads();

        // ---- phase G: scatter + output ----
        if (o < G_ * K_) {
            int g = o >> 4, k = o & 15;
            #pragma unroll
            for (int v = 0; v < NB; v++)
                atomicAdd(&g_cent[(b * G_ + g) * N_ + s->idxs[v][k]], s->att[v][g][k]);
        }
        #pragma unroll
        for (int v = 0; v < NB; v++) {
            float og = 0.f;
            #pragma unroll
            for (int k = 0; k < K_; k++)
                og += tf32r(s->att[v][gq][k]) * tf32r(lv[v][k]);
            s->outbuf[o][it * NB + v] = og;
        }
        __syncthreads();
    }

    // ---- flush outputs coalesced per-row (2x float4) ----
    {
        float4* dst = (float4*)&out[((size_t)(b * COUT_ + o)) * N_ + n0];
        float* rowp = s->outbuf[o];
        dst[0] = make_float4(rowp[0], rowp[1], rowp[2], rowp[3]);
        dst[1] = make_float4(rowp[4], rowp[5], rowp[6], rowp[7]);
    }
}

// ---------------- kernel 2: top-16 per (b,g), desc, tie -> lower index ----------------
__global__ __launch_bounds__(256) void k_topk() {
    const int bg  = blockIdx.x;
    const int tid = threadIdx.x;
    __shared__ float v_s[N_];
    __shared__ float rv[256];
    __shared__ int   ri[256];

    for (int i = tid; i < N_; i += 256) v_s[i] = g_cent[bg * N_ + i];
    __syncthreads();

    for (int t = 0; t < K_; t++) {
        float bv = -1e30f; int bi = N_;
        for (int i = tid; i < N_; i += 256) {
            float v = v_s[i];
            if (v > bv || (v == bv && i < bi)) { bv = v; bi = i; }
        }
        rv[tid] = bv; ri[tid] = bi;
        __syncthreads();
        for (int sdist = 128; sdist > 0; sdist >>= 1) {
            if (tid < sdist) {
                if (rv[tid + sdist] > rv[tid] ||
                    (rv[tid + sdist] == rv[tid] && ri[tid + sdist] < ri[tid])) {
                    rv[tid] = rv[tid + sdist]; ri[tid] = ri[tid + sdist];
                }
            }
            __syncthreads();
        }
        if (tid == 0) {
            g_vals[bg * K_ + t] = rv[0];
            g_inds[bg * K_ + t] = ri[0];
            v_s[ri[0]] = -1e30f;
        }
        __syncthreads();
    }
}

// ---------------- kernel 3: non-local prep per (b,g) ----------------
__global__ __launch_bounds__(256) void k_nl_prep(
    const float* __restrict__ abs_x,
    const float* __restrict__ points,
    const float* __restrict__ npe_b1,
    const float* __restrict__ npe_b2)
{
    const int bg = blockIdx.x;
    const int b = bg / G_, g = bg % G_;
    const int tid = threadIdx.x;

    __shared__ int   inds_s[K_];
    __shared__ float rel_s[3][K_];
    __shared__ float h2_s[K_][CNL_];

    if (tid < K_) {
        inds_s[tid] = g_inds[bg * K_ + tid];
        g_tanhvals[bg * K_ + tid] = tanhf(g_vals[bg * K_ + tid]);
    }
    __syncthreads();
    if (tid < 3 * K_) {
        int c = tid / K_, j = tid % K_;
        rel_s[c][j] = tf32r(points[(b * 3 + c) * N_ + inds_s[j]]
                          - points[(b * 3 + c) * N_ + inds_s[0]]);
    }
    __syncthreads();
    {   // h2 (tf32 dot, K=3)
        int j = tid / CNL_, d = tid % CNL_;
        float h = npe_b1[g * CNL_ + d];
        #pragma unroll
        for (int c = 0; c < 3; c++) h += rel_s[c][j] * r_npe_w1[(g * 3 + c) * CNL_ + d];
        h2_s[j][d] = tf32r(h > 0.f ? h : 0.f);
    }
    __syncthreads();
    {   // pe_nl + gathered nk/nv2 (tf32 dots)
        int c = tid / K_, j = tid % K_;
        float pe = npe_b2[g * CNL_ + c];
        #pragma unroll
        for (int d = 0; d < CNL_; d++) pe += h2_s[j][d] * r_npe_w2[(g * CNL_ + d) * CNL_ + c];
        int nn = inds_s[j];
        float nk = 0.f, nv2 = 0.f;
        const int row = g * CNL_ + c;
        #pragma unroll 8
        for (int cc = 0; cc < 64; cc++) {
            float a = tf32r(abs_x[(b * 64 + cc) * N_ + nn]);
            nk  += rT_Wnk[cc * NL_ + row]  * a;
            nv2 += rT_Wnv2[cc * NL_ + row] * a;
        }
        g_M[bg * CNL_ * K_ + c * K_ + j]    = nk + pe;
        g_nv2j[bg * CNL_ * K_ + c * K_ + j] = nv2;
    }
}

// ---------------- kernel 4: non-local main, per (b,n) ----------------
__global__ __launch_bounds__(64) void k_nl_main(
    const float* __restrict__ abs_x,
    float*       __restrict__ out)
{
    const int blk = blockIdx.x;
    const int b   = blk / (N_ / TN2);
    const int n0  = (blk % (N_ / TN2)) * TN2;
    const int tid = threadIdx.x;       // 0..63
    const int g = tid / CNL_, c = tid % CNL_;

    __shared__ float M_s[G_ * CNL_ * K_];
    __shared__ float nv2j_s[G_ * CNL_ * K_];
    __shared__ float tv_s[G_ * K_];
    __shared__ float a2_s[64];
    __shared__ float nq_s[G_][CNL_];
    __shared__ float score_s[G_][K_];
    __shared__ float w_s[G_][K_];
    __shared__ float ssum_s[G_];

    for (int i = tid; i < G_ * CNL_ * K_; i += 64) {
        M_s[i]    = tf32r(g_M[b * G_ * CNL_ * K_ + i]);
        nv2j_s[i] = tf32r(g_nv2j[b * G_ * CNL_ * K_ + i]);
    }
    if (tid < G_ * K_) tv_s[tid] = g_tanhvals[b * G_ * K_ + tid];
    __syncthreads();

    for (int nt = 0; nt < TN2; nt++) {
        const int n = n0 + nt;
        a2_s[tid] = tf32r(abs_x[(b * 64 + tid) * N_ + n]);
        __syncthreads();

        float nq = 0.f, nv1 = 0.f, nv2 = 0.f;
        #pragma unroll 8
        for (int cc = 0; cc < 64; cc++) {
            float a = a2_s[cc];
            nq  += rT_Wnq[cc * NL_ + tid]  * a;
            nv1 += rT_Wnv1[cc * NL_ + tid] * a;
            nv2 += rT_Wnv2[cc * NL_ + tid] * a;
        }
        nq_s[g][c] = tf32r(nq);
        __syncthreads();

        {   // score (tf32 dot)
            float sc = 0.f;
            #pragma unroll
            for (int c2 = 0; c2 < CNL_; c2++)
                sc += nq_s[g][c2] * M_s[g * CNL_ * K_ + c2 * K_ + c];
            score_s[g][c] = sc;
        }
        __syncthreads();
        if (c == 0) {
            float m = -1e30f;
            #pragma unroll
            for (int j = 0; j < K_; j++) m = fmaxf(m, score_s[g][j]);
            float sum = 0.f; float e[K_];
            #pragma unroll
            for (int j = 0; j < K_; j++) { e[j] = expf(score_s[g][j] - m); sum += e[j]; }
            float inv = 1.f / sum;
            float ws = 0.f;
            #pragma unroll
            for (int j = 0; j < K_; j++) {
                float w = e[j] * inv * tv_s[g * K_ + j];
                w_s[g][j] = w; ws += w;
            }
            ssum_s[g] = ws;
        }
        __syncthreads();

        float og = (nv1 - nv2) * ssum_s[g];
        #pragma unroll
        for (int j = 0; j < K_; j++)
            og += tf32r(w_s[g][j]) * nv2j_s[g * CNL_ * K_ + c * K_ + j];
        out[((size_t)b * COUT_ + L_ + tid) * N_ + n] = og;
        __syncthreads();
    }
}

// ---------------- launcher ----------------
extern "C" void kernel_launch(void* const* d_in, const int* in_sizes, int n_in,
                              void* d_out, int out_size) {
    const float* x      = (const float*)d_in[0];
    const float* abs_x  = (const float*)d_in[1];
    const float* points = (const float*)d_in[2];
    const float* Wq     = (const float*)d_in[3];
    const float* Wk     = (const float*)d_in[4];
    const float* Wv     = (const float*)d_in[5];
    const float* Wnq    = (const float*)d_in[6];
    const float* Wnk    = (const float*)d_in[7];
    const float* Wnv1   = (const float*)d_in[8];
    const float* Wnv2   = (const float*)d_in[9];
    const float* pe_w1  = (const float*)d_in[10];
    const float* pe_b1  = (const float*)d_in[11];
    const float* pe_w2  = (const float*)d_in[12];
    const float* pe_b2  = (const float*)d_in[13];
    const float* npe_w1 = (const float*)d_in[14];
    const float* npe_b1 = (const float*)d_in[15];
    const float* npe_w2 = (const float*)d_in[16];
    const float* npe_b2 = (const float*)d_in[17];
    const int*   idx    = (const int*)d_in[18];
    float* out = (float*)d_out;

    static int smem_set = 0;
    if (!smem_set) {
        cudaFuncSetAttribute(k_local, cudaFuncAttributeMaxDynamicSharedMemorySize,
                             (int)sizeof(LocalSmem));
        smem_set = 1;
    }

    k_prep<<<128, 256>>>(Wq, Wk, Wv, pe_w1, pe_w2, Wnq, Wnk, Wnv1, Wnv2, npe_w1, npe_w2);
    k_local<<<B_ * (N_ / TILE_N), L_, sizeof(LocalSmem)>>>(x, abs_x, points,
                                                           pe_b1, pe_b2, idx, out);
    k_topk<<<B_ * G_, 256>>>();
    k_nl_prep<<<B_ * G_, 256>>>(abs_x, points, npe_b1, npe_b2);
    k_nl_main<<<B_ * (N_ / TN2), 64>>>(abs_x, out);
}

// round 4
// speedup vs baseline: 10.4839x; 4.1156x over previous
#include <cuda_runtime.h>
#include <math.h>
#include <stdint.h>

#define B_    8
#define CIN_  128
#define N_    2048
#define K_    16
#define G_    4
#define L_    192
#define NL_   64
#define CL_   48
#define CNL_  16
#define COUT_ 256
#define TN    16      // n-tile per CTA in k_local
#define THR   512
#define TN2   16

// ---------------- tf32 rounding (emulate cuBLAS TF32 operand conversion) ----------------
__device__ __forceinline__ float tf32r(float a) {
    uint32_t u;
    asm("cvt.rna.tf32.f32 %0, %1;" : "=r"(u) : "f"(a));
    return __uint_as_float(u);
}

// ---------------- scratch (device globals) ----------------
__device__ float g_cent[B_ * G_ * N_];
__device__ float g_vals[B_ * G_ * K_];
__device__ int   g_inds[B_ * G_ * K_];
__device__ float g_M[B_ * G_ * CNL_ * K_];
__device__ float g_nv2j[B_ * G_ * CNL_ * K_];
__device__ float g_tanhvals[B_ * G_ * K_];

// pre-rounded (tf32) weights in access-optimal layouts
__device__ float  rT_Wq[64 * L_];        // [c][o]
__device__ float  r_Wk[L_ * 64];         // [o][cc]   (for k-tilde)
__device__ float  rT_Wv[CIN_ * L_];      // [cc][o]
__device__ float  rT_pe_w2[L_ * L_];     // [c][d]  = tf32r(pe_w2[d][c])
__device__ float4 g_w1pack[L_];          // {w1x,w1y,w1z,b1} per d (w rounded, b raw)
__device__ float  rT_Wnq[64 * NL_];
__device__ float  rT_Wnk[64 * NL_];
__device__ float  rT_Wnv1[64 * NL_];
__device__ float  rT_Wnv2[64 * NL_];
__device__ float  r_npe_w1[G_ * 3 * CNL_];
__device__ float  r_npe_w2[G_ * CNL_ * CNL_];

// ---------------- kernel: round/transpose weights, zero cent ----------------
__global__ void k_prep(const float* __restrict__ Wq, const float* __restrict__ Wk,
                       const float* __restrict__ Wv,
                       const float* __restrict__ pe_w1, const float* __restrict__ pe_b1,
                       const float* __restrict__ pe_w2,
                       const float* __restrict__ Wnq, const float* __restrict__ Wnk,
                       const float* __restrict__ Wnv1, const float* __restrict__ Wnv2,
                       const float* __restrict__ npe_w1, const float* __restrict__ npe_w2) {
    int tid = blockIdx.x * blockDim.x + threadIdx.x;
    int nth = gridDim.x * blockDim.x;
    for (int i = tid; i < 64 * L_; i += nth) {
        int c = i / L_, o = i % L_;
        rT_Wq[i] = tf32r(Wq[o * 64 + c]);
    }
    for (int i = tid; i < L_ * 64; i += nth) r_Wk[i] = tf32r(Wk[i]);
    for (int i = tid; i < CIN_ * L_; i += nth) {
        int c = i / L_, o = i % L_;
        rT_Wv[i] = tf32r(Wv[o * CIN_ + c]);
    }
    for (int i = tid; i < L_ * L_; i += nth) {
        int c = i / L_, d = i % L_;
        rT_pe_w2[i] = tf32r(pe_w2[d * L_ + c]);
    }
    for (int d = tid; d < L_; d += nth) {
        g_w1pack[d] = make_float4(tf32r(pe_w1[d]), tf32r(pe_w1[L_ + d]),
                                  tf32r(pe_w1[2 * L_ + d]), pe_b1[d]);
    }
    for (int i = tid; i < 64 * NL_; i += nth) {
        int c = i / NL_, o = i % NL_;
        rT_Wnq[i]  = tf32r(Wnq[o * 64 + c]);
        rT_Wnk[i]  = tf32r(Wnk[o * 64 + c]);
        rT_Wnv1[i] = tf32r(Wnv1[o * 64 + c]);
        rT_Wnv2[i] = tf32r(Wnv2[o * 64 + c]);
    }
    for (int i = tid; i < G_ * 3 * CNL_; i += nth)    r_npe_w1[i] = tf32r(npe_w1[i]);
    for (int i = tid; i < G_ * CNL_ * CNL_; i += nth) r_npe_w2[i] = tf32r(npe_w2[i]);
    for (int i = tid; i < B_ * G_ * N_; i += nth) g_cent[i] = 0.f;
}

// ---------------- k_local smem ----------------
#define XPAD 257       // 256 + 1 word: conflict-free column access
#define QPAD 65        // 64 + 1
#define LPAD 20        // 16 + 4, keeps 16B alignment for float4 reads

struct __align__(16) LocalSmem {
    float x[CIN_ * XPAD];        // [cc][n*16+k] raw          131584 B
    float qt[96 * QPAD];         // [dloc][n*4+g]              24960 B  (xa overlays qt+kt)
    float kt[64 * QPAD];         // [cc][n*4+g]                16640 B
    float lq[L_ * LPAD];         // [o][n]                     15360 B  (outbuf overlays)
    float absx[64][TN];          // rounded                     4096 B
    float rel[TN][K_][4];        // [n][k][axis] rounded        4096 B
    float part[2][G_][TN][K_];   // score partials              8192 B
    float att[G_][TN][K_];       // raw att                     4096 B
    float bconst[G_][TN];        //                              256 B
    int   idxs[TN][K_];          //                             1024 B
};

// ---------------- kernel 1: fused local branch (regrouped) ----------------
__global__ __launch_bounds__(THR) void k_local(
    const float* __restrict__ x,
    const float* __restrict__ abs_x,
    const float* __restrict__ points,
    const float* __restrict__ pe_b2,
    const int*   __restrict__ idx,
    float*       __restrict__ out)
{
    extern __shared__ char smem_raw[];
    LocalSmem* s = (LocalSmem*)smem_raw;

    const int blk = blockIdx.x;
    const int b   = blk >> 7;              // / 128
    const int n0  = (blk & 127) * TN;
    const int tid = threadIdx.x;

    // ================= phase A: loads =================
    {
        const float* xb = x + ((size_t)(b * CIN_) * N_ + n0) * K_;
        for (int i = tid; i < CIN_ * 64; i += THR) {   // 64 float4 per cc row
            int cc = i >> 6, q = i & 63;
            float4 v = *(const float4*)(xb + (size_t)cc * N_ * K_ + q * 4);
            float* dst = &s->x[cc * XPAD + q * 4];
            dst[0] = v.x; dst[1] = v.y; dst[2] = v.z; dst[3] = v.w;
        }
        for (int i = tid; i < 64 * TN; i += THR) {
            int c = i >> 4, n = i & 15;
            s->absx[c][n] = tf32r(abs_x[(b * 64 + c) * N_ + n0 + n]);
        }
        if (tid < TN * K_) {
            int n = tid >> 4, k = tid & 15;
            s->idxs[n][k] = idx[(b * N_ + n0 + n) * K_ + k];
        }
    }
    __syncthreads();

    // ================= phase B: lq + rel gather =================
    if (tid < 384) {
        const int o = tid % 192, nh = tid / 192;
        float acc[8];
        #pragma unroll
        for (int j = 0; j < 8; j++) acc[j] = 0.f;
        #pragma unroll 4
        for (int c = 0; c < 64; c++) {
            float w = rT_Wq[c * L_ + o];
            const float4* ap = (const float4*)&s->absx[c][nh * 8];
            float4 a0 = ap[0], a1 = ap[1];
            acc[0] += w * a0.x; acc[1] += w * a0.y; acc[2] += w * a0.z; acc[3] += w * a0.w;
            acc[4] += w * a1.x; acc[5] += w * a1.y; acc[6] += w * a1.z; acc[7] += w * a1.w;
        }
        #pragma unroll
        for (int j = 0; j < 8; j++) s->lq[o * LPAD + nh * 8 + j] = acc[j];
    } else {
        int t = tid - 384;
        for (int r = t; r < 3 * TN * K_; r += 128) {
            int ax = r >> 8, rem = r & 255, n = rem >> 4, k = rem & 15;
            float p  = points[(b * 3 + ax) * N_ + s->idxs[n][k]];
            float p0 = points[(b * 3 + ax) * N_ + s->idxs[n][0]];
            s->rel[n][k][ax] = tf32r(p - p0);
        }
    }
    __syncthreads();

    // ---- qt task helper (macro-ish lambda) ----
    auto qt_task = [&](int id, int dbase) {
        int g = id / 192, rr = id % 192;
        int dloc = rr >> 1, nh = rr & 1;
        int d = dbase + dloc;
        float acc[8];
        #pragma unroll
        for (int j = 0; j < 8; j++) acc[j] = 0.f;
        const float* wcol = &rT_pe_w2[(g * CL_) * L_ + d];
        #pragma unroll 4
        for (int c = 0; c < CL_; c++) {
            float w = wcol[c * L_];
            const float4* lp = (const float4*)&s->lq[(g * CL_ + c) * LPAD + nh * 8];
            float4 l0 = lp[0], l1 = lp[1];
            acc[0] += w * l0.x; acc[1] += w * l0.y; acc[2] += w * l0.z; acc[3] += w * l0.w;
            acc[4] += w * l1.x; acc[5] += w * l1.y; acc[6] += w * l1.z; acc[7] += w * l1.w;
        }
        #pragma unroll
        for (int j = 0; j < 8; j++)
            s->qt[dloc * QPAD + (nh * 8 + j) * 4 + g] = acc[j];
    };

    // ================= phase C0: qt(d<96) + kt =================
    qt_task(tid, 0);
    if (tid < 256) {
        qt_task(512 + tid, 0);
    } else {
        int id = tid - 256;           // kt task: 256 = 4g x 64cc
        int g = id >> 6, cc = id & 63;
        float acc[16];
        #pragma unroll
        for (int j = 0; j < 16; j++) acc[j] = 0.f;
        #pragma unroll 4
        for (int c = 0; c < CL_; c++) {
            float w = r_Wk[(g * CL_ + c) * 64 + cc];
            const float4* lp = (const float4*)&s->lq[(g * CL_ + c) * LPAD];
            float4 l0 = lp[0], l1 = lp[1], l2 = lp[2], l3 = lp[3];
            acc[0]  += w * l0.x; acc[1]  += w * l0.y; acc[2]  += w * l0.z; acc[3]  += w * l0.w;
            acc[4]  += w * l1.x; acc[5]  += w * l1.y; acc[6]  += w * l1.z; acc[7]  += w * l1.w;
            acc[8]  += w * l2.x; acc[9]  += w * l2.y; acc[10] += w * l2.z; acc[11] += w * l2.w;
            acc[12] += w * l3.x; acc[13] += w * l3.y; acc[14] += w * l3.z; acc[15] += w * l3.w;
        }
        #pragma unroll
        for (int j = 0; j < 16; j++) s->kt[cc * QPAD + j * 4 + g] = acc[j];
    }
    __syncthreads();

    // ---- S_pe partial helper ----
    auto spe_half = [&](int n, int k, int dstart, int dloc0, float* acc) {
        float rx = s->rel[n][k][0], ry = s->rel[n][k][1], rz = s->rel[n][k][2];
        #pragma unroll 4
        for (int dd = 0; dd < 48; dd++) {
            int d = dstart + dd;
            float4 wp = g_w1pack[d];
            float hv = rx * wp.x + ry * wp.y + rz * wp.z + wp.w;
            hv = hv > 0.f ? hv : 0.f;
            hv = tf32r(hv);
            const float* qp = &s->qt[(dloc0 + dd) * QPAD + n * 4];
            acc[0] += qp[0] * hv; acc[1] += qp[1] * hv;
            acc[2] += qp[2] * hv; acc[3] += qp[3] * hv;
        }
    };

    // ================= phase D0: S_pe(d<96) + S_k =================
    {
        int dq = tid >> 8, r = tid & 255, n = r >> 4, k = r & 15;
        float acc[4] = {0.f, 0.f, 0.f, 0.f};
        spe_half(n, k, dq * 48, dq * 48, acc);
        // S_k half: cc in [dq*32, dq*32+32)
        #pragma unroll 4
        for (int cc = dq * 32; cc < dq * 32 + 32; cc++) {
            float lo = s->x[cc * XPAD + n * 16 + k];
            float hi = s->x[(cc + 64) * XPAD + n * 16 + k];
            float xsv = tf32r(lo + hi);
            const float* kp = &s->kt[cc * QPAD + n * 4];
            acc[0] += kp[0] * xsv; acc[1] += kp[1] * xsv;
            acc[2] += kp[2] * xsv; acc[3] += kp[3] * xsv;
        }
        #pragma unroll
        for (int g = 0; g < 4; g++) s->part[dq][g][n][k] = acc[g];
    }
    __syncthreads();

    // ================= phase C1: qt(d>=96) + bconst =================
    qt_task(tid, 96);
    if (tid >= 256) {
        qt_task(512 + (tid - 256), 96);
    } else if (tid < 64) {
        int g = tid >> 4, n = tid & 15;
        float sum = 0.f;
        #pragma unroll 8
        for (int c = 0; c < CL_; c++)
            sum += s->lq[(g * CL_ + c) * LPAD + n] * pe_b2[g * CL_ + c];
        s->bconst[g][n] = sum;
    }
    __syncthreads();

    // ================= phase D1: S_pe(d>=96), accumulate =================
    {
        int dq = tid >> 8, r = tid & 255, n = r >> 4, k = r & 15;
        float acc[4] = {0.f, 0.f, 0.f, 0.f};
        spe_half(n, k, 96 + dq * 48, dq * 48, acc);
        #pragma unroll
        for (int g = 0; g < 4; g++) s->part[dq][g][n][k] += acc[g];
    }
    __syncthreads();

    // ================= phase E: combine + softmax =================
    if (tid < 64) {
        int g = tid >> 4, n = tid & 15;
        float sc[K_];
        float m = -1e30f;
        #pragma unroll
        for (int k = 0; k < K_; k++) {
            sc[k] = s->part[0][g][n][k] + s->part[1][g][n][k] + s->bconst[g][n];
            m = fmaxf(m, sc[k]);
        }
        float sum = 0.f;
        #pragma unroll
        for (int k = 0; k < K_; k++) { sc[k] = expf(sc[k] - m); sum += sc[k]; }
        float inv = 1.f / sum;
        #pragma unroll
        for (int k = 0; k < K_; k++) s->att[g][n][k] = sc[k] * inv;
    }
    __syncthreads();

    // ================= phase F: scatter + xa =================
    {
        // scatter (raw att)
        for (int t = tid; t < G_ * TN * K_; t += THR) {
            int g = t >> 8, rem = t & 255, n = rem >> 4, k = rem & 15;
            atomicAdd(&g_cent[(b * G_ + g) * N_ + s->idxs[n][k]], s->att[g][n][k]);
        }
        // xa[g][cc][n] = sum_k tf32r(att) * tf32r(x)
        float* xa = &s->qt[0];   // overlays qt+kt (41.6KB >= 40.96KB)
        int cc = tid & 127, nset = tid >> 7;
        for (int ni = 0; ni < 4; ni++) {
            int n = nset * 4 + ni;
            float acc[4] = {0.f, 0.f, 0.f, 0.f};
            #pragma unroll
            for (int k = 0; k < K_; k++) {
                float xv = tf32r(s->x[cc * XPAD + n * 16 + k]);
                acc[0] += tf32r(s->att[0][n][k]) * xv;
                acc[1] += tf32r(s->att[1][n][k]) * xv;
                acc[2] += tf32r(s->att[2][n][k]) * xv;
                acc[3] += tf32r(s->att[3][n][k]) * xv;
            }
            #pragma unroll
            for (int g = 0; g < 4; g++) xa[(g * CIN_ + cc) * LPAD + n] = acc[g];
        }
    }
    __syncthreads();

    // ================= phase G: out = Wv^T-dot(xa) =================
    if (tid < 384) {
        const float* xa = &s->qt[0];
        int o = tid % 192, nh = tid / 192;
        int g = o / CL_;
        float acc[8];
        #pragma unroll
        for (int j = 0; j < 8; j++) acc[j] = 0.f;
        #pragma unroll 4
        for (int cc = 0; cc < CIN_; cc++) {
            float w = rT_Wv[cc * L_ + o];
            const float4* xp = (const float4*)&xa[(g * CIN_ + cc) * LPAD + nh * 8];
            float4 x0 = xp[0], x1 = xp[1];
            acc[0] += w * x0.x; acc[1] += w * x0.y; acc[2] += w * x0.z; acc[3] += w * x0.w;
            acc[4] += w * x1.x; acc[5] += w * x1.y; acc[6] += w * x1.z; acc[7] += w * x1.w;
        }
        float* outbuf = &s->lq[0];
        #pragma unroll
        for (int j = 0; j < 8; j++) outbuf[o * LPAD + nh * 8 + j] = acc[j];
    }
    __syncthreads();

    // store coalesced
    {
        const float* outbuf = &s->lq[0];
        for (int t = tid; t < L_ * 4; t += THR) {
            int o = t >> 2, q = t & 3;
            const float* rp = &outbuf[o * LPAD + q * 4];
            float4 v = make_float4(rp[0], rp[1], rp[2], rp[3]);
            *(float4*)&out[((size_t)(b * COUT_ + o)) * N_ + n0 + q * 4] = v;
        }
    }
}

// ---------------- kernel 2: top-16 per (b,g), desc, tie -> lower index ----------------
__global__ __launch_bounds__(256) void k_topk() {
    const int bg  = blockIdx.x;
    const int tid = threadIdx.x;
    __shared__ float v_s[N_];
    __shared__ float rv[256];
    __shared__ int   ri[256];

    for (int i = tid; i < N_; i += 256) v_s[i] = g_cent[bg * N_ + i];
    __syncthreads();

    for (int t = 0; t < K_; t++) {
        float bv = -1e30f; int bi = N_;
        for (int i = tid; i < N_; i += 256) {
            float v = v_s[i];
            if (v > bv || (v == bv && i < bi)) { bv = v; bi = i; }
        }
        rv[tid] = bv; ri[tid] = bi;
        __syncthreads();
        for (int sd = 128; sd > 0; sd >>= 1) {
            if (tid < sd) {
                if (rv[tid + sd] > rv[tid] ||
                    (rv[tid + sd] == rv[tid] && ri[tid + sd] < ri[tid])) {
                    rv[tid] = rv[tid + sd]; ri[tid] = ri[tid + sd];
                }
            }
            __syncthreads();
        }
        if (tid == 0) {
            g_vals[bg * K_ + t] = rv[0];
            g_inds[bg * K_ + t] = ri[0];
            v_s[ri[0]] = -1e30f;
        }
        __syncthreads();
    }
}

// ---------------- kernel 3: non-local prep per (b,g) ----------------
__global__ __launch_bounds__(256) void k_nl_prep(
    const float* __restrict__ abs_x,
    const float* __restrict__ points,
    const float* __restrict__ npe_b1,
    const float* __restrict__ npe_b2)
{
    const int bg = blockIdx.x;
    const int b = bg / G_, g = bg % G_;
    const int tid = threadIdx.x;

    __shared__ int   inds_s[K_];
    __shared__ float rel_s[3][K_];
    __shared__ float h2_s[K_][CNL_];

    if (tid < K_) {
        inds_s[tid] = g_inds[bg * K_ + tid];
        g_tanhvals[bg * K_ + tid] = tanhf(g_vals[bg * K_ + tid]);
    }
    __syncthreads();
    if (tid < 3 * K_) {
        int c = tid / K_, j = tid % K_;
        rel_s[c][j] = tf32r(points[(b * 3 + c) * N_ + inds_s[j]]
                          - points[(b * 3 + c) * N_ + inds_s[0]]);
    }
    __syncthreads();
    {
        int j = tid / CNL_, d = tid % CNL_;
        float h = npe_b1[g * CNL_ + d];
        #pragma unroll
        for (int c = 0; c < 3; c++) h += rel_s[c][j] * r_npe_w1[(g * 3 + c) * CNL_ + d];
        h2_s[j][d] = tf32r(h > 0.f ? h : 0.f);
    }
    __syncthreads();
    {
        int c = tid / K_, j = tid % K_;
        float pe = npe_b2[g * CNL_ + c];
        #pragma unroll
        for (int d = 0; d < CNL_; d++) pe += h2_s[j][d] * r_npe_w2[(g * CNL_ + d) * CNL_ + c];
        int nn = inds_s[j];
        float nk = 0.f, nv2 = 0.f;
        const int row = g * CNL_ + c;
        #pragma unroll 8
        for (int cc = 0; cc < 64; cc++) {
            float a = tf32r(abs_x[(b * 64 + cc) * N_ + nn]);
            nk  += rT_Wnk[cc * NL_ + row]  * a;
            nv2 += rT_Wnv2[cc * NL_ + row] * a;
        }
        g_M[bg * CNL_ * K_ + c * K_ + j]    = nk + pe;
        g_nv2j[bg * CNL_ * K_ + c * K_ + j] = nv2;
    }
}

// ---------------- kernel 4: non-local main ----------------
__global__ __launch_bounds__(64) void k_nl_main(
    const float* __restrict__ abs_x,
    float*       __restrict__ out)
{
    const int blk = blockIdx.x;
    const int b   = blk / (N_ / TN2);
    const int n0  = (blk % (N_ / TN2)) * TN2;
    const int tid = threadIdx.x;
    const int g = tid / CNL_, c = tid % CNL_;

    __shared__ float M_s[G_ * CNL_ * K_];
    __shared__ float nv2j_s[G_ * CNL_ * K_];
    __shared__ float tv_s[G_ * K_];
    __shared__ float a2_s[64];
    __shared__ float nq_s[G_][CNL_];
    __shared__ float score_s[G_][K_];
    __shared__ float w_s[G_][K_];
    __shared__ float ssum_s[G_];

    for (int i = tid; i < G_ * CNL_ * K_; i += 64) {
        M_s[i]    = tf32r(g_M[b * G_ * CNL_ * K_ + i]);
        nv2j_s[i] = tf32r(g_nv2j[b * G_ * CNL_ * K_ + i]);
    }
    if (tid < G_ * K_) tv_s[tid] = g_tanhvals[b * G_ * K_ + tid];
    __syncthreads();

    for (int nt = 0; nt < TN2; nt++) {
        const int n = n0 + nt;
        a2_s[tid] = tf32r(abs_x[(b * 64 + tid) * N_ + n]);
        __syncthreads();

        float nq = 0.f, nv1 = 0.f, nv2 = 0.f;
        #pragma unroll 8
        for (int cc = 0; cc < 64; cc++) {
            float a = a2_s[cc];
            nq  += rT_Wnq[cc * NL_ + tid]  * a;
            nv1 += rT_Wnv1[cc * NL_ + tid] * a;
            nv2 += rT_Wnv2[cc * NL_ + tid] * a;
        }
        nq_s[g][c] = tf32r(nq);
        __syncthreads();

        {
            float sc = 0.f;
            #pragma unroll
            for (int c2 = 0; c2 < CNL_; c2++)
                sc += nq_s[g][c2] * M_s[g * CNL_ * K_ + c2 * K_ + c];
            score_s[g][c] = sc;
        }
        __syncthreads();
        if (c == 0) {
            float m = -1e30f;
            #pragma unroll
            for (int j = 0; j < K_; j++) m = fmaxf(m, score_s[g][j]);
            float sum = 0.f; float e[K_];
            #pragma unroll
            for (int j = 0; j < K_; j++) { e[j] = expf(score_s[g][j] - m); sum += e[j]; }
            float inv = 1.f / sum;
            float ws = 0.f;
            #pragma unroll
            for (int j = 0; j < K_; j++) {
                float w = e[j] * inv * tv_s[g * K_ + j];
                w_s[g][j] = w; ws += w;
            }
            ssum_s[g] = ws;
        }
        __syncthreads();

        float og = (nv1 - nv2) * ssum_s[g];
        #pragma unroll
        for (int j = 0; j < K_; j++)
            og += tf32r(w_s[g][j]) * nv2j_s[g * CNL_ * K_ + c * K_ + j];
        out[((size_t)b * COUT_ + L_ + tid) * N_ + n] = og;
        __syncthreads();
    }
}

// ---------------- launcher ----------------
extern "C" void kernel_launch(void* const* d_in, const int* in_sizes, int n_in,
                              void* d_out, int out_size) {
    const float* x      = (const float*)d_in[0];
    const float* abs_x  = (const float*)d_in[1];
    const float* points = (const float*)d_in[2];
    const float* Wq     = (const float*)d_in[3];
    const float* Wk     = (const float*)d_in[4];
    const float* Wv     = (const float*)d_in[5];
    const float* Wnq    = (const float*)d_in[6];
    const float* Wnk    = (const float*)d_in[7];
    const float* Wnv1   = (const float*)d_in[8];
    const float* Wnv2   = (const float*)d_in[9];
    const float* pe_w1  = (const float*)d_in[10];
    const float* pe_b1  = (const float*)d_in[11];
    const float* pe_w2  = (const float*)d_in[12];
    const float* pe_b2  = (const float*)d_in[13];
    const float* npe_w1 = (const float*)d_in[14];
    const float* npe_b1 = (const float*)d_in[15];
    const float* npe_w2 = (const float*)d_in[16];
    const float* npe_b2 = (const float*)d_in[17];
    const int*   idx    = (const int*)d_in[18];
    float* out = (float*)d_out;

    static int smem_set = 0;
    if (!smem_set) {
        cudaFuncSetAttribute(k_local, cudaFuncAttributeMaxDynamicSharedMemorySize,
                             (int)sizeof(LocalSmem));
        smem_set = 1;
    }

    k_prep<<<128, 256>>>(Wq, Wk, Wv, pe_w1, pe_b1, pe_w2,
                         Wnq, Wnk, Wnv1, Wnv2, npe_w1, npe_w2);
    k_local<<<B_ * (N_ / TN), THR, sizeof(LocalSmem)>>>(x, abs_x, points,
                                                        pe_b2, idx, out);
    k_topk<<<B_ * G_, 256>>>();
    k_nl_prep<<<B_ * G_, 256>>>(abs_x, points, npe_b1, npe_b2);
    k_nl_main<<<B_ * (N_ / TN2), 64>>>(abs_x, out);
}

// round 6
// speedup vs baseline: 11.5071x; 1.0976x over previous
#include <cuda_runtime.h>
#include <math.h>
#include <stdint.h>

#define B_    8
#define CIN_  128
#define N_    2048
#define K_    16
#define G_    4
#define L_    192
#define NL_   64
#define CL_   48
#define CNL_  16
#define COUT_ 256
#define TN    16      // n-tile per CTA in k_local
#define THR   512
#define TNL   64      // n-tile per CTA in k_nl_main

// ---------------- tf32 rounding (emulate cuBLAS TF32 operand conversion) ----------------
__device__ __forceinline__ float tf32r(float a) {
    uint32_t u;
    asm("cvt.rna.tf32.f32 %0, %1;" : "=r"(u) : "f"(a));
    return __uint_as_float(u);
}

// ---------------- scratch (device globals) ----------------
__device__ float g_cent[B_ * G_ * N_];
__device__ float g_vals[B_ * G_ * K_];
__device__ int   g_inds[B_ * G_ * K_];
__device__ float g_M[B_ * G_ * CNL_ * K_];
__device__ float g_nv2j[B_ * G_ * CNL_ * K_];
__device__ float g_tanhvals[B_ * G_ * K_];

// pre-rounded (tf32) weights in access-optimal layouts
__device__ float  rT_Wq[64 * L_];        // [c][o]
__device__ float  r_Wk[L_ * 64];         // [o][cc]   (for k-tilde)
__device__ float  rT_Wv[CIN_ * L_];      // [cc][o]
__device__ float  rT_pe_w2[L_ * L_];     // [c][d]  = tf32r(pe_w2[d][c])
__device__ float4 g_w1pack[L_];          // {w1x,w1y,w1z,b1} per d (w rounded, b raw)
__device__ float  rT_Wnq[64 * NL_];
__device__ float  rT_Wnk[64 * NL_];
__device__ float  rT_Wnv1[64 * NL_];
__device__ float  rT_Wnv2[64 * NL_];
__device__ float  r_npe_w1[G_ * 3 * CNL_];
__device__ float  r_npe_w2[G_ * CNL_ * CNL_];

// ---------------- kernel: round/transpose weights, zero cent ----------------
__global__ void k_prep(const float* __restrict__ Wq, const float* __restrict__ Wk,
                       const float* __restrict__ Wv,
                       const float* __restrict__ pe_w1, const float* __restrict__ pe_b1,
                       const float* __restrict__ pe_w2,
                       const float* __restrict__ Wnq, const float* __restrict__ Wnk,
                       const float* __restrict__ Wnv1, const float* __restrict__ Wnv2,
                       const float* __restrict__ npe_w1, const float* __restrict__ npe_w2) {
    int tid = blockIdx.x * blockDim.x + threadIdx.x;
    int nth = gridDim.x * blockDim.x;
    for (int i = tid; i < 64 * L_; i += nth) {
        int c = i / L_, o = i % L_;
        rT_Wq[i] = tf32r(Wq[o * 64 + c]);
    }
    for (int i = tid; i < L_ * 64; i += nth) r_Wk[i] = tf32r(Wk[i]);
    for (int i = tid; i < CIN_ * L_; i += nth) {
        int c = i / L_, o = i % L_;
        rT_Wv[i] = tf32r(Wv[o * CIN_ + c]);
    }
    for (int i = tid; i < L_ * L_; i += nth) {
        int c = i / L_, d = i % L_;
        rT_pe_w2[i] = tf32r(pe_w2[d * L_ + c]);
    }
    for (int d = tid; d < L_; d += nth) {
        g_w1pack[d] = make_float4(tf32r(pe_w1[d]), tf32r(pe_w1[L_ + d]),
                                  tf32r(pe_w1[2 * L_ + d]), pe_b1[d]);
    }
    for (int i = tid; i < 64 * NL_; i += nth) {
        int c = i / NL_, o = i % NL_;
        rT_Wnq[i]  = tf32r(Wnq[o * 64 + c]);
        rT_Wnk[i]  = tf32r(Wnk[o * 64 + c]);
        rT_Wnv1[i] = tf32r(Wnv1[o * 64 + c]);
        rT_Wnv2[i] = tf32r(Wnv2[o * 64 + c]);
    }
    for (int i = tid; i < G_ * 3 * CNL_; i += nth)    r_npe_w1[i] = tf32r(npe_w1[i]);
    for (int i = tid; i < G_ * CNL_ * CNL_; i += nth) r_npe_w2[i] = tf32r(npe_w2[i]);
    for (int i = tid; i < B_ * G_ * N_; i += nth) g_cent[i] = 0.f;
}

// ---------------- k_local smem ----------------
#define XPAD 257       // 256 + 1 word: conflict-free column access
#define QPAD 65        // 64 + 1
#define LPAD 20        // 16 + 4, keeps 16B alignment for float4 reads

struct __align__(16) LocalSmem {
    float x[CIN_ * XPAD];        // [cc][n*16+k] raw
    float qt[96 * QPAD];         // [dloc][n*4+g]   (xa overlays qt+kt)
    float kt[64 * QPAD];         // [cc][n*4+g]
    float lq[L_ * LPAD];         // [o][n]          (outbuf overlays)
    float absx[64][TN];
    float rel[TN][K_][4];
    float part[2][G_][TN][K_];
    float att[G_][TN][K_];
    float bconst[G_][TN];
    int   idxs[TN][K_];
};

// ---------------- kernel 1: fused local branch (regrouped) ----------------
__global__ __launch_bounds__(THR) void k_local(
    const float* __restrict__ x,
    const float* __restrict__ abs_x,
    const float* __restrict__ points,
    const float* __restrict__ pe_b2,
    const int*   __restrict__ idx,
    float*       __restrict__ out)
{
    extern __shared__ char smem_raw[];
    LocalSmem* s = (LocalSmem*)smem_raw;

    const int blk = blockIdx.x;
    const int b   = blk >> 7;
    const int n0  = (blk & 127) * TN;
    const int tid = threadIdx.x;

    // ================= phase A: loads =================
    {
        const float* xb = x + ((size_t)(b * CIN_) * N_ + n0) * K_;
        for (int i = tid; i < CIN_ * 64; i += THR) {
            int cc = i >> 6, q = i & 63;
            float4 v = *(const float4*)(xb + (size_t)cc * N_ * K_ + q * 4);
            float* dst = &s->x[cc * XPAD + q * 4];
            dst[0] = v.x; dst[1] = v.y; dst[2] = v.z; dst[3] = v.w;
        }
        for (int i = tid; i < 64 * TN; i += THR) {
            int c = i >> 4, n = i & 15;
            s->absx[c][n] = tf32r(abs_x[(b * 64 + c) * N_ + n0 + n]);
        }
        if (tid < TN * K_) {
            int n = tid >> 4, k = tid & 15;
            s->idxs[n][k] = idx[(b * N_ + n0 + n) * K_ + k];
        }
    }
    __syncthreads();

    // ================= phase B: lq + rel gather =================
    if (tid < 384) {
        const int o = tid % 192, nh = tid / 192;
        float acc[8];
        #pragma unroll
        for (int j = 0; j < 8; j++) acc[j] = 0.f;
        #pragma unroll 4
        for (int c = 0; c < 64; c++) {
            float w = rT_Wq[c * L_ + o];
            const float4* ap = (const float4*)&s->absx[c][nh * 8];
            float4 a0 = ap[0], a1 = ap[1];
            acc[0] += w * a0.x; acc[1] += w * a0.y; acc[2] += w * a0.z; acc[3] += w * a0.w;
            acc[4] += w * a1.x; acc[5] += w * a1.y; acc[6] += w * a1.z; acc[7] += w * a1.w;
        }
        #pragma unroll
        for (int j = 0; j < 8; j++) s->lq[o * LPAD + nh * 8 + j] = acc[j];
    } else {
        int t = tid - 384;
        for (int r = t; r < 3 * TN * K_; r += 128) {
            int ax = r >> 8, rem = r & 255, n = rem >> 4, k = rem & 15;
            float p  = points[(b * 3 + ax) * N_ + s->idxs[n][k]];
            float p0 = points[(b * 3 + ax) * N_ + s->idxs[n][0]];
            s->rel[n][k][ax] = tf32r(p - p0);
        }
    }
    __syncthreads();

    auto qt_task = [&](int id, int dbase) {
        int g = id / 192, rr = id % 192;
        int dloc = rr >> 1, nh = rr & 1;
        int d = dbase + dloc;
        float acc[8];
        #pragma unroll
        for (int j = 0; j < 8; j++) acc[j] = 0.f;
        const float* wcol = &rT_pe_w2[(g * CL_) * L_ + d];
        #pragma unroll 4
        for (int c = 0; c < CL_; c++) {
            float w = wcol[c * L_];
            const float4* lp = (const float4*)&s->lq[(g * CL_ + c) * LPAD + nh * 8];
            float4 l0 = lp[0], l1 = lp[1];
            acc[0] += w * l0.x; acc[1] += w * l0.y; acc[2] += w * l0.z; acc[3] += w * l0.w;
            acc[4] += w * l1.x; acc[5] += w * l1.y; acc[6] += w * l1.z; acc[7] += w * l1.w;
        }
        #pragma unroll
        for (int j = 0; j < 8; j++)
            s->qt[dloc * QPAD + (nh * 8 + j) * 4 + g] = acc[j];
    };

    // ================= phase C0: qt(d<96) + kt =================
    qt_task(tid, 0);
    if (tid < 256) {
        qt_task(512 + tid, 0);
    } else {
        int id = tid - 256;
        int g = id >> 6, cc = id & 63;
        float acc[16];
        #pragma unroll
        for (int j = 0; j < 16; j++) acc[j] = 0.f;
        #pragma unroll 4
        for (int c = 0; c < CL_; c++) {
            float w = r_Wk[(g * CL_ + c) * 64 + cc];
            const float4* lp = (const float4*)&s->lq[(g * CL_ + c) * LPAD];
            float4 l0 = lp[0], l1 = lp[1], l2 = lp[2], l3 = lp[3];
            acc[0]  += w * l0.x; acc[1]  += w * l0.y; acc[2]  += w * l0.z; acc[3]  += w * l0.w;
            acc[4]  += w * l1.x; acc[5]  += w * l1.y; acc[6]  += w * l1.z; acc[7]  += w * l1.w;
            acc[8]  += w * l2.x; acc[9]  += w * l2.y; acc[10] += w * l2.z; acc[11] += w * l2.w;
            acc[12] += w * l3.x; acc[13] += w * l3.y; acc[14] += w * l3.z; acc[15] += w * l3.w;
        }
        #pragma unroll
        for (int j = 0; j < 16; j++) s->kt[cc * QPAD + j * 4 + g] = acc[j];
    }
    __syncthreads();

    auto spe_half = [&](int n, int k, int dstart, int dloc0, float* acc) {
        float rx = s->rel[n][k][0], ry = s->rel[n][k][1], rz = s->rel[n][k][2];
        #pragma unroll 4
        for (int dd = 0; dd < 48; dd++) {
            int d = dstart + dd;
            float4 wp = g_w1pack[d];
            float hv = rx * wp.x + ry * wp.y + rz * wp.z + wp.w;
            hv = hv > 0.f ? hv : 0.f;
            hv = tf32r(hv);
            const float* qp = &s->qt[(dloc0 + dd) * QPAD + n * 4];
            acc[0] += qp[0] * hv; acc[1] += qp[1] * hv;
            acc[2] += qp[2] * hv; acc[3] += qp[3] * hv;
        }
    };

    // ================= phase D0: S_pe(d<96) + S_k =================
    {
        int dq = tid >> 8, r = tid & 255, n = r >> 4, k = r & 15;
        float acc[4] = {0.f, 0.f, 0.f, 0.f};
        spe_half(n, k, dq * 48, dq * 48, acc);
        #pragma unroll 4
        for (int cc = dq * 32; cc < dq * 32 + 32; cc++) {
            float lo = s->x[cc * XPAD + n * 16 + k];
            float hi = s->x[(cc + 64) * XPAD + n * 16 + k];
            float xsv = tf32r(lo + hi);
            const float* kp = &s->kt[cc * QPAD + n * 4];
            acc[0] += kp[0] * xsv; acc[1] += kp[1] * xsv;
            acc[2] += kp[2] * xsv; acc[3] += kp[3] * xsv;
        }
        #pragma unroll
        for (int g = 0; g < 4; g++) s->part[dq][g][n][k] = acc[g];
    }
    __syncthreads();

    // ================= phase C1: qt(d>=96) + bconst =================
    qt_task(tid, 96);
    if (tid >= 256) {
        qt_task(512 + (tid - 256), 96);
    } else if (tid < 64) {
        int g = tid >> 4, n = tid & 15;
        float sum = 0.f;
        #pragma unroll 8
        for (int c = 0; c < CL_; c++)
            sum += s->lq[(g * CL_ + c) * LPAD + n] * pe_b2[g * CL_ + c];
        s->bconst[g][n] = sum;
    }
    __syncthreads();

    // ================= phase D1: S_pe(d>=96), accumulate =================
    {
        int dq = tid >> 8, r = tid & 255, n = r >> 4, k = r & 15;
        float acc[4] = {0.f, 0.f, 0.f, 0.f};
        spe_half(n, k, 96 + dq * 48, dq * 48, acc);
        #pragma unroll
        for (int g = 0; g < 4; g++) s->part[dq][g][n][k] += acc[g];
    }
    __syncthreads();

    // ================= phase E: combine + softmax =================
    if (tid < 64) {
        int g = tid >> 4, n = tid & 15;
        float sc[K_];
        float m = -1e30f;
        #pragma unroll
        for (int k = 0; k < K_; k++) {
            sc[k] = s->part[0][g][n][k] + s->part[1][g][n][k] + s->bconst[g][n];
            m = fmaxf(m, sc[k]);
        }
        float sum = 0.f;
        #pragma unroll
        for (int k = 0; k < K_; k++) { sc[k] = expf(sc[k] - m); sum += sc[k]; }
        float inv = 1.f / sum;
        #pragma unroll
        for (int k = 0; k < K_; k++) s->att[g][n][k] = sc[k] * inv;
    }
    __syncthreads();

    // ================= phase F: scatter + xa =================
    {
        for (int t = tid; t < G_ * TN * K_; t += THR) {
            int g = t >> 8, rem = t & 255, n = rem >> 4, k = rem & 15;
            atomicAdd(&g_cent[(b * G_ + g) * N_ + s->idxs[n][k]], s->att[g][n][k]);
        }
        float* xa = &s->qt[0];
        int cc = tid & 127, nset = tid >> 7;
        for (int ni = 0; ni < 4; ni++) {
            int n = nset * 4 + ni;
            float acc[4] = {0.f, 0.f, 0.f, 0.f};
            #pragma unroll
            for (int k = 0; k < K_; k++) {
                float xv = tf32r(s->x[cc * XPAD + n * 16 + k]);
                acc[0] += tf32r(s->att[0][n][k]) * xv;
                acc[1] += tf32r(s->att[1][n][k]) * xv;
                acc[2] += tf32r(s->att[2][n][k]) * xv;
                acc[3] += tf32r(s->att[3][n][k]) * xv;
            }
            #pragma unroll
            for (int g = 0; g < 4; g++) xa[(g * CIN_ + cc) * LPAD + n] = acc[g];
        }
    }
    __syncthreads();

    // ================= phase G: out = Wv^T-dot(xa) =================
    if (tid < 384) {
        const float* xa = &s->qt[0];
        int o = tid % 192, nh = tid / 192;
        int g = o / CL_;
        float acc[8];
        #pragma unroll
        for (int j = 0; j < 8; j++) acc[j] = 0.f;
        #pragma unroll 4
        for (int cc = 0; cc < CIN_; cc++) {
            float w = rT_Wv[cc * L_ + o];
            const float4* xp = (const float4*)&xa[(g * CIN_ + cc) * LPAD + nh * 8];
            float4 x0 = xp[0], x1 = xp[1];
            acc[0] += w * x0.x; acc[1] += w * x0.y; acc[2] += w * x0.z; acc[3] += w * x0.w;
            acc[4] += w * x1.x; acc[5] += w * x1.y; acc[6] += w * x1.z; acc[7] += w * x1.w;
        }
        float* outbuf = &s->lq[0];
        #pragma unroll
        for (int j = 0; j < 8; j++) outbuf[o * LPAD + nh * 8 + j] = acc[j];
    }
    __syncthreads();

    {
        const float* outbuf = &s->lq[0];
        for (int t = tid; t < L_ * 4; t += THR) {
            int o = t >> 2, q = t & 3;
            const float* rp = &outbuf[o * LPAD + q * 4];
            float4 v = make_float4(rp[0], rp[1], rp[2], rp[3]);
            *(float4*)&out[((size_t)(b * COUT_ + o)) * N_ + n0 + q * 4] = v;
        }
    }
}

// ---------------- kernel 2: top-16 per (b,g), desc, tie -> lower index ----------------
__global__ __launch_bounds__(256) void k_topk() {
    const int bg  = blockIdx.x;
    const int tid = threadIdx.x;
    __shared__ float v_s[N_];
    __shared__ float rv[256];
    __shared__ int   ri[256];

    for (int i = tid; i < N_; i += 256) v_s[i] = g_cent[bg * N_ + i];
    __syncthreads();

    for (int t = 0; t < K_; t++) {
        float bv = -1e30f; int bi = N_;
        for (int i = tid; i < N_; i += 256) {
            float v = v_s[i];
            if (v > bv || (v == bv && i < bi)) { bv = v; bi = i; }
        }
        rv[tid] = bv; ri[tid] = bi;
        __syncthreads();
        for (int sd = 128; sd > 0; sd >>= 1) {
            if (tid < sd) {
                if (rv[tid + sd] > rv[tid] ||
                    (rv[tid + sd] == rv[tid] && ri[tid + sd] < ri[tid])) {
                    rv[tid] = rv[tid + sd]; ri[tid] = ri[tid + sd];
                }
            }
            __syncthreads();
        }
        if (tid == 0) {
            g_vals[bg * K_ + t] = rv[0];
            g_inds[bg * K_ + t] = ri[0];
            v_s[ri[0]] = -1e30f;
        }
        __syncthreads();
    }
}

// ---------------- kernel 3: non-local prep per (b,g) ----------------
__global__ __launch_bounds__(256) void k_nl_prep(
    const float* __restrict__ abs_x,
    const float* __restrict__ points,
    const float* __restrict__ npe_b1,
    const float* __restrict__ npe_b2)
{
    const int bg = blockIdx.x;
    const int b = bg / G_, g = bg % G_;
    const int tid = threadIdx.x;

    __shared__ int   inds_s[K_];
    __shared__ float rel_s[3][K_];
    __shared__ float h2_s[K_][CNL_];

    if (tid < K_) {
        inds_s[tid] = g_inds[bg * K_ + tid];
        g_tanhvals[bg * K_ + tid] = tanhf(g_vals[bg * K_ + tid]);
    }
    __syncthreads();
    if (tid < 3 * K_) {
        int c = tid / K_, j = tid % K_;
        rel_s[c][j] = tf32r(points[(b * 3 + c) * N_ + inds_s[j]]
                          - points[(b * 3 + c) * N_ + inds_s[0]]);
    }
    __syncthreads();
    {
        int j = tid / CNL_, d = tid % CNL_;
        float h = npe_b1[g * CNL_ + d];
        #pragma unroll
        for (int c = 0; c < 3; c++) h += rel_s[c][j] * r_npe_w1[(g * 3 + c) * CNL_ + d];
        h2_s[j][d] = tf32r(h > 0.f ? h : 0.f);
    }
    __syncthreads();
    {
        int c = tid / K_, j = tid % K_;
        float pe = npe_b2[g * CNL_ + c];
        #pragma unroll
        for (int d = 0; d < CNL_; d++) pe += h2_s[j][d] * r_npe_w2[(g * CNL_ + d) * CNL_ + c];
        int nn = inds_s[j];
        float nk = 0.f, nv2 = 0.f;
        const int row = g * CNL_ + c;
        #pragma unroll 8
        for (int cc = 0; cc < 64; cc++) {
            float a = tf32r(abs_x[(b * 64 + cc) * N_ + nn]);
            nk  += rT_Wnk[cc * NL_ + row]  * a;
            nv2 += rT_Wnv2[cc * NL_ + row] * a;
        }
        g_M[bg * CNL_ * K_ + c * K_ + j]    = nk + pe;
        g_nv2j[bg * CNL_ * K_ + c * K_ + j] = nv2;
    }
}

// ---------------- kernel 4: non-local main (smem-staged, shuffle subgroups) ----------------
struct __align__(16) NLSmem {
    float wnq[64 * 64];          // [cc][o]
    float wnv1[64 * 64];
    float wnv2[64 * 64];
    float M[G_][CNL_ * K_];      // [g][c2*16+j] rounded
    float nv2jT[G_][K_ * CNL_];  // [g][j*16+c] rounded
    float tv[G_ * K_];
    float a2[64][4];             // rounded, 4 n-slots
    float outbuf[64 * 65];       // padded rows
};

__global__ __launch_bounds__(256) void k_nl_main(
    const float* __restrict__ abs_x,
    float*       __restrict__ out)
{
    extern __shared__ char smraw[];
    NLSmem* s = (NLSmem*)smraw;

    const int blk = blockIdx.x;
    const int b   = blk / (N_ / TNL);
    const int n0  = (blk % (N_ / TNL)) * TNL;
    const int tid = threadIdx.x;
    const int warp  = tid >> 5;
    const int half  = (tid >> 4) & 1;
    const int c     = tid & 15;
    const int g     = (warp & 1) * 2 + half;   // warp-pair covers g 0..3
    const int nslot = warp >> 1;               // 0..3
    const int o     = g * CNL_ + c;

    // ---- stage weights + per-b tensors (once) ----
    for (int i = tid; i < 64 * 64; i += 256) {
        s->wnq[i]  = rT_Wnq[i];
        s->wnv1[i] = rT_Wnv1[i];
        s->wnv2[i] = rT_Wnv2[i];
    }
    for (int i = tid; i < G_ * CNL_ * K_; i += 256) {
        float mv = tf32r(g_M[b * G_ * CNL_ * K_ + i]);
        s->M[0][i] = mv;
        int gg = i >> 8, rem = i & 255, cc2 = rem >> 4, jj = rem & 15;
        s->nv2jT[gg][jj * 16 + cc2] = tf32r(g_nv2j[b * G_ * CNL_ * K_ + i]);
    }
    if (tid < G_ * K_) s->tv[tid] = g_tanhvals[b * G_ * K_ + tid];
    __syncthreads();

    const float tvj = s->tv[g * K_ + c];

    for (int it = 0; it < TNL / 4; it++) {
        const int nb = n0 + it * 4;
        {   // coalesced a2 tile (rounded)
            int cc = tid >> 2, nn = tid & 3;
            s->a2[cc][nn] = tf32r(abs_x[(b * 64 + cc) * N_ + nb + nn]);
        }
        __syncthreads();

        float nq = 0.f, nv1 = 0.f, nv2 = 0.f;
        #pragma unroll 8
        for (int cc = 0; cc < 64; cc++) {
            float a = s->a2[cc][nslot];
            nq  += s->wnq[cc * 64 + o]  * a;
            nv1 += s->wnv1[cc * 64 + o] * a;
            nv2 += s->wnv2[cc * 64 + o] * a;
        }
        float nqr = tf32r(nq);

        // score: lane c = key-slot; ordered over c2
        float sc = 0.f;
        const float* Mg = s->M[g];
        #pragma unroll
        for (int c2 = 0; c2 < CNL_; c2++) {
            float v = __shfl_sync(0xffffffffu, nqr, c2, 16);
            sc += v * Mg[c2 * 16 + c];
        }
        // ordered softmax (gather in j order -> identical arithmetic)
        float m = -1e30f;
        #pragma unroll
        for (int j = 0; j < K_; j++) m = fmaxf(m, __shfl_sync(0xffffffffu, sc, j, 16));
        float e = expf(sc - m);
        float sum = 0.f;
        #pragma unroll
        for (int j = 0; j < K_; j++) sum += __shfl_sync(0xffffffffu, e, j, 16);
        float inv = 1.f / sum;
        float w = e * inv * tvj;
        float ws = 0.f;
        #pragma unroll
        for (int j = 0; j < K_; j++) ws += __shfl_sync(0xffffffffu, w, j, 16);

        float og = (nv1 - nv2) * ws;
        const float* nvg = s->nv2jT[g];
        #pragma unroll
        for (int j = 0; j < K_; j++) {
            float wj = tf32r(__shfl_sync(0xffffffffu, w, j, 16));
            og += wj * nvg[j * 16 + c];
        }
        s->outbuf[o * 65 + it * 4 + nslot] = og;
        __syncthreads();
    }

    // ---- coalesced flush ----
    for (int t = tid; t < 64 * 16; t += 256) {
        int o2 = t >> 4, q = t & 15;
        const float* rp = &s->outbuf[o2 * 65 + q * 4];
        float4 v = make_float4(rp[0], rp[1], rp[2], rp[3]);
        *(float4*)&out[((size_t)(b * COUT_ + L_ + o2)) * N_ + n0 + q * 4] = v;
    }
}

// ---------------- launcher ----------------
extern "C" void kernel_launch(void* const* d_in, const int* in_sizes, int n_in,
                              void* d_out, int out_size) {
    const float* x      = (const float*)d_in[0];
    const float* abs_x  = (const float*)d_in[1];
    const float* points = (const float*)d_in[2];
    const float* Wq     = (const float*)d_in[3];
    const float* Wk     = (const float*)d_in[4];
    const float* Wv     = (const float*)d_in[5];
    const float* Wnq    = (const float*)d_in[6];
    const float* Wnk    = (const float*)d_in[7];
    const float* Wnv1   = (const float*)d_in[8];
    const float* Wnv2   = (const float*)d_in[9];
    const float* pe_w1  = (const float*)d_in[10];
    const float* pe_b1  = (const float*)d_in[11];
    const float* pe_w2  = (const float*)d_in[12];
    const float* pe_b2  = (const float*)d_in[13];
    const float* npe_w1 = (const float*)d_in[14];
    const float* npe_b1 = (const float*)d_in[15];
    const float* npe_w2 = (const float*)d_in[16];
    const float* npe_b2 = (const float*)d_in[17];
    const int*   idx    = (const int*)d_in[18];
    float* out = (float*)d_out;

    static int smem_set = 0;
    if (!smem_set) {
        cudaFuncSetAttribute(k_local, cudaFuncAttributeMaxDynamicSharedMemorySize,
                             (int)sizeof(LocalSmem));
        cudaFuncSetAttribute(k_nl_main, cudaFuncAttributeMaxDynamicSharedMemorySize,
                             (int)sizeof(NLSmem));
        smem_set = 1;
    }

    k_prep<<<128, 256>>>(Wq, Wk, Wv, pe_w1, pe_b1, pe_w2,
                         Wnq, Wnk, Wnv1, Wnv2, npe_w1, npe_w2);
    k_local<<<B_ * (N_ / TN), THR, sizeof(LocalSmem)>>>(x, abs_x, points,
                                                        pe_b2, idx, out);
    k_topk<<<B_ * G_, 256>>>();
    k_nl_prep<<<B_ * G_, 256>>>(abs_x, points, npe_b1, npe_b2);
    k_nl_main<<<B_ * (N_ / TNL), 256, sizeof(NLSmem)>>>(abs_x, out);
}

// round 8
// speedup vs baseline: 12.0689x; 1.0488x over previous
#include <cuda_runtime.h>
#include <math.h>
#include <stdint.h>

#define B_    8
#define CIN_  128
#define N_    2048
#define K_    16
#define G_    4
#define L_    192
#define NL_   64
#define CL_   48
#define CNL_  16
#define COUT_ 256
#define TN    8       // n-tile per CTA in k_local
#define THR   256
#define TNL   64      // n-tile per CTA in k_nl_main

// ---------------- tf32 rounding (emulate cuBLAS TF32 operand conversion) ----------------
__device__ __forceinline__ float tf32r(float a) {
    uint32_t u;
    asm("cvt.rna.tf32.f32 %0, %1;" : "=r"(u) : "f"(a));
    return __uint_as_float(u);
}

// ---------------- scratch (device globals) ----------------
__device__ float g_cent[B_ * G_ * N_];
__device__ float g_vals[B_ * G_ * K_];
__device__ int   g_inds[B_ * G_ * K_];
__device__ float g_M[B_ * G_ * CNL_ * K_];
__device__ float g_nv2j[B_ * G_ * CNL_ * K_];
__device__ float g_tanhvals[B_ * G_ * K_];

// pre-rounded (tf32) weights in access-optimal layouts
__device__ float  rT_Wq[64 * L_];        // [c][o]
__device__ float  r_Wk[L_ * 64];         // [o][cc]
__device__ float  rT_Wv[CIN_ * L_];      // [cc][o]
__device__ float  rT_pe_w2[L_ * L_];     // [c][d]
__device__ float4 g_w1pack[L_];          // {w1x,w1y,w1z,b1}
__device__ float  rT_Wnq[64 * NL_];
__device__ float  rT_Wnk[64 * NL_];
__device__ float  rT_Wnv1[64 * NL_];
__device__ float  rT_Wnv2[64 * NL_];
__device__ float  r_npe_w1[G_ * 3 * CNL_];
__device__ float  r_npe_w2[G_ * CNL_ * CNL_];

// ---------------- kernel: round/transpose weights, zero cent ----------------
__global__ void k_prep(const float* __restrict__ Wq, const float* __restrict__ Wk,
                       const float* __restrict__ Wv,
                       const float* __restrict__ pe_w1, const float* __restrict__ pe_b1,
                       const float* __restrict__ pe_w2,
                       const float* __restrict__ Wnq, const float* __restrict__ Wnk,
                       const float* __restrict__ Wnv1, const float* __restrict__ Wnv2,
                       const float* __restrict__ npe_w1, const float* __restrict__ npe_w2) {
    int tid = blockIdx.x * blockDim.x + threadIdx.x;
    int nth = gridDim.x * blockDim.x;
    for (int i = tid; i < 64 * L_; i += nth) {
        int c = i / L_, o = i % L_;
        rT_Wq[i] = tf32r(Wq[o * 64 + c]);
    }
    for (int i = tid; i < L_ * 64; i += nth) r_Wk[i] = tf32r(Wk[i]);
    for (int i = tid; i < CIN_ * L_; i += nth) {
        int c = i / L_, o = i % L_;
        rT_Wv[i] = tf32r(Wv[o * CIN_ + c]);
    }
    for (int i = tid; i < L_ * L_; i += nth) {
        int c = i / L_, d = i % L_;
        rT_pe_w2[i] = tf32r(pe_w2[d * L_ + c]);
    }
    for (int d = tid; d < L_; d += nth) {
        g_w1pack[d] = make_float4(tf32r(pe_w1[d]), tf32r(pe_w1[L_ + d]),
                                  tf32r(pe_w1[2 * L_ + d]), pe_b1[d]);
    }
    for (int i = tid; i < 64 * NL_; i += nth) {
        int c = i / NL_, o = i % NL_;
        rT_Wnq[i]  = tf32r(Wnq[o * 64 + c]);
        rT_Wnk[i]  = tf32r(Wnk[o * 64 + c]);
        rT_Wnv1[i] = tf32r(Wnv1[o * 64 + c]);
        rT_Wnv2[i] = tf32r(Wnv2[o * 64 + c]);
    }
    for (int i = tid; i < G_ * 3 * CNL_; i += nth)    r_npe_w1[i] = tf32r(npe_w1[i]);
    for (int i = tid; i < G_ * CNL_ * CNL_; i += nth) r_npe_w2[i] = tf32r(npe_w2[i]);
    for (int i = tid; i < B_ * G_ * N_; i += nth) g_cent[i] = 0.f;
}

// ---------------- k_local smem (TN=8) ----------------
#define XROW (TN * K_)       // 128
#define XPAD (XROW + 1)      // 129, conflict-free column access
#define QPAD (TN * G_ + 1)   // 33
#define LPAD 12              // 8 + 4, rows stay 16B aligned (48B stride)
#define XAPAD 9              // xa row pad (odd -> conflict-free)

struct __align__(16) LocalSmem {
    float x[CIN_ * XPAD];        // raw x tile                66048 B
    float qt[96 * QPAD];         // [dloc][n*4+g]             12672 B  (xa overlays qt+kt)
    float kt[64 * QPAD];         // [cc][n*4+g]                8448 B
    float lq[L_ * LPAD];         // [o][n]                     9216 B  (outbuf overlays)
    float absx[64][TN];          //                            2048 B
    float rel[TN][K_][4];        //                            2048 B
    float part[2][G_][TN][K_];   //                            4096 B
    float att[G_][TN][K_];       // raw att                    2048 B
    float attr[G_][TN][K_];      // tf32-rounded att           2048 B
    float bconst[G_][TN];        //                             256 B
    int   idxs[TN][K_];          //                             512 B
};

// ---------------- kernel 1: fused local branch (regrouped, 2 CTA/SM) ----------------
__global__ __launch_bounds__(THR) void k_local(
    const float* __restrict__ x,
    const float* __restrict__ abs_x,
    const float* __restrict__ points,
    const float* __restrict__ pe_b2,
    const int*   __restrict__ idx,
    float*       __restrict__ out)
{
    extern __shared__ char smem_raw[];
    LocalSmem* s = (LocalSmem*)smem_raw;

    const int blk = blockIdx.x;
    const int b   = blk >> 8;              // / 256
    const int n0  = (blk & 255) * TN;
    const int tid = threadIdx.x;

    // ================= phase A: loads =================
    {
        const float* xb = x + ((size_t)(b * CIN_) * N_ + n0) * K_;
        for (int i = tid; i < CIN_ * 32; i += THR) {   // 32 float4 per cc row
            int cc = i >> 5, q = i & 31;
            float4 v = *(const float4*)(xb + (size_t)cc * N_ * K_ + q * 4);
            float* dst = &s->x[cc * XPAD + q * 4];
            dst[0] = v.x; dst[1] = v.y; dst[2] = v.z; dst[3] = v.w;
        }
        for (int i = tid; i < 64 * TN; i += THR) {
            int c = i >> 3, n = i & 7;
            s->absx[c][n] = tf32r(abs_x[(b * 64 + c) * N_ + n0 + n]);
        }
        if (tid < TN * K_) {
            int n = tid >> 4, k = tid & 15;
            s->idxs[n][k] = idx[(b * N_ + n0 + n) * K_ + k];
        }
    }
    __syncthreads();

    // ================= phase B: lq (192 thr) + rel gather (64 thr) =================
    if (tid < 192) {
        const int o = tid;
        float acc[8];
        #pragma unroll
        for (int j = 0; j < 8; j++) acc[j] = 0.f;
        #pragma unroll 4
        for (int c = 0; c < 64; c++) {
            float w = rT_Wq[c * L_ + o];
            const float4* ap = (const float4*)&s->absx[c][0];
            float4 a0 = ap[0], a1 = ap[1];
            acc[0] += w * a0.x; acc[1] += w * a0.y; acc[2] += w * a0.z; acc[3] += w * a0.w;
            acc[4] += w * a1.x; acc[5] += w * a1.y; acc[6] += w * a1.z; acc[7] += w * a1.w;
        }
        #pragma unroll
        for (int j = 0; j < 8; j++) s->lq[o * LPAD + j] = acc[j];
    } else {
        int t = tid - 192;
        for (int r = t; r < 3 * TN * K_; r += 64) {     // 384 elems
            int ax = r >> 7, rem = r & 127, n = rem >> 4, k = rem & 15;
            float p  = points[(b * 3 + ax) * N_ + s->idxs[n][k]];
            float p0 = points[(b * 3 + ax) * N_ + s->idxs[n][0]];
            s->rel[n][k][ax] = tf32r(p - p0);
        }
    }
    __syncthreads();

    // ---- qt task: one thread handles (g, dloc), all 8 n ----
    auto qt_task = [&](int g, int dloc, int dbase) {
        int d = dbase + dloc;
        float acc[8];
        #pragma unroll
        for (int j = 0; j < 8; j++) acc[j] = 0.f;
        const float* wcol = &rT_pe_w2[(g * CL_) * L_ + d];
        #pragma unroll 4
        for (int c = 0; c < CL_; c++) {
            float w = wcol[c * L_];
            const float4* lp = (const float4*)&s->lq[(g * CL_ + c) * LPAD];
            float4 l0 = lp[0], l1 = lp[1];
            acc[0] += w * l0.x; acc[1] += w * l0.y; acc[2] += w * l0.z; acc[3] += w * l0.w;
            acc[4] += w * l1.x; acc[5] += w * l1.y; acc[6] += w * l1.z; acc[7] += w * l1.w;
        }
        #pragma unroll
        for (int j = 0; j < 8; j++)
            s->qt[dloc * QPAD + j * 4 + g] = acc[j];
    };

    // ================= phase C0: qt(d<96) [384 tasks] + kt [256 tasks] =================
    for (int t = tid; t < 640; t += THR) {
        if (t < 384) {
            qt_task(t / 96, t % 96, 0);
        } else {
            int t2 = t - 384;
            int g = t2 >> 6, cc = t2 & 63;
            float acc[8];
            #pragma unroll
            for (int j = 0; j < 8; j++) acc[j] = 0.f;
            #pragma unroll 4
            for (int c = 0; c < CL_; c++) {
                float w = r_Wk[(g * CL_ + c) * 64 + cc];
                const float4* lp = (const float4*)&s->lq[(g * CL_ + c) * LPAD];
                float4 l0 = lp[0], l1 = lp[1];
                acc[0] += w * l0.x; acc[1] += w * l0.y; acc[2] += w * l0.z; acc[3] += w * l0.w;
                acc[4] += w * l1.x; acc[5] += w * l1.y; acc[6] += w * l1.z; acc[7] += w * l1.w;
            }
            #pragma unroll
            for (int j = 0; j < 8; j++) s->kt[cc * QPAD + j * 4 + g] = acc[j];
        }
    }
    __syncthreads();

    auto spe_half = [&](int n, int k, int dstart, int dloc0, float* acc) {
        float rx = s->rel[n][k][0], ry = s->rel[n][k][1], rz = s->rel[n][k][2];
        #pragma unroll 4
        for (int dd = 0; dd < 48; dd++) {
            int d = dstart + dd;
            float4 wp = g_w1pack[d];
            float hv = rx * wp.x + ry * wp.y + rz * wp.z + wp.w;
            hv = hv > 0.f ? hv : 0.f;
            hv = tf32r(hv);
            const float* qp = &s->qt[(dloc0 + dd) * QPAD + n * 4];
            acc[0] += qp[0] * hv; acc[1] += qp[1] * hv;
            acc[2] += qp[2] * hv; acc[3] += qp[3] * hv;
        }
    };

    // ================= phase D0: S_pe(d<96) + S_k  (256 = 2dq x 8n x 16k) =================
    {
        int dq = tid >> 7, r = tid & 127, n = r >> 4, k = r & 15;
        float acc[4] = {0.f, 0.f, 0.f, 0.f};
        spe_half(n, k, dq * 48, dq * 48, acc);
        #pragma unroll 4
        for (int cc = dq * 32; cc < dq * 32 + 32; cc++) {
            float lo = s->x[cc * XPAD + n * 16 + k];
            float hi = s->x[(cc + 64) * XPAD + n * 16 + k];
            float xsv = tf32r(lo + hi);
            const float* kp = &s->kt[cc * QPAD + n * 4];
            acc[0] += kp[0] * xsv; acc[1] += kp[1] * xsv;
            acc[2] += kp[2] * xsv; acc[3] += kp[3] * xsv;
        }
        #pragma unroll
        for (int g = 0; g < 4; g++) s->part[dq][g][n][k] = acc[g];
    }
    __syncthreads();

    // ================= phase C1: qt(d>=96) [384] + bconst [32] =================
    for (int t = tid; t < 416; t += THR) {
        if (t < 384) {
            qt_task(t / 96, t % 96, 96);
        } else {
            int t2 = t - 384;
            int g = t2 >> 3, n = t2 & 7;
            float sum = 0.f;
            #pragma unroll 8
            for (int c = 0; c < CL_; c++)
                sum += s->lq[(g * CL_ + c) * LPAD + n] * pe_b2[g * CL_ + c];
            s->bconst[g][n] = sum;
        }
    }
    __syncthreads();

    // ================= phase D1: S_pe(d>=96), accumulate =================
    {
        int dq = tid >> 7, r = tid & 127, n = r >> 4, k = r & 15;
        float acc[4] = {0.f, 0.f, 0.f, 0.f};
        spe_half(n, k, 96 + dq * 48, dq * 48, acc);
        #pragma unroll
        for (int g = 0; g < 4; g++) s->part[dq][g][n][k] += acc[g];
    }
    __syncthreads();

    // ================= phase E: combine + softmax (32 tasks) =================
    if (tid < G_ * TN) {
        int g = tid >> 3, n = tid & 7;
        float sc[K_];
        float m = -1e30f;
        #pragma unroll
        for (int k = 0; k < K_; k++) {
            sc[k] = s->part[0][g][n][k] + s->part[1][g][n][k] + s->bconst[g][n];
            m = fmaxf(m, sc[k]);
        }
        float sum = 0.f;
        #pragma unroll
        for (int k = 0; k < K_; k++) { sc[k] = expf(sc[k] - m); sum += sc[k]; }
        float inv = 1.f / sum;
        #pragma unroll
        for (int k = 0; k < K_; k++) {
            float a = sc[k] * inv;
            s->att[g][n][k]  = a;
            s->attr[g][n][k] = tf32r(a);
        }
    }
    __syncthreads();

    // ================= phase F: scatter + xa =================
    {
        for (int t = tid; t < G_ * TN * K_; t += THR) {   // 512 atomics
            int g = t >> 7, rem = t & 127, n = rem >> 4, k = rem & 15;
            atomicAdd(&g_cent[(b * G_ + g) * N_ + s->idxs[n][k]], s->att[g][n][k]);
        }
        float* xa = &s->qt[0];   // overlays qt+kt (21120B >= 512*9*4=18432B)
        int cc = tid & 127, nset = tid >> 7;              // nset 0..1
        for (int ni = 0; ni < 4; ni++) {
            int n = nset * 4 + ni;
            float acc[4] = {0.f, 0.f, 0.f, 0.f};
            #pragma unroll
            for (int k = 0; k < K_; k++) {
                float xv = tf32r(s->x[cc * XPAD + n * 16 + k]);
                acc[0] += s->attr[0][n][k] * xv;
                acc[1] += s->attr[1][n][k] * xv;
                acc[2] += s->attr[2][n][k] * xv;
                acc[3] += s->attr[3][n][k] * xv;
            }
            #pragma unroll
            for (int g = 0; g < 4; g++) xa[(g * CIN_ + cc) * XAPAD + n] = acc[g];
        }
    }
    __syncthreads();

    // ================= phase G: out = Wv^T-dot(xa) (192 thr) =================
    if (tid < 192) {
        const float* xa = &s->qt[0];
        int o = tid;
        int g = o / CL_;
        float acc[8];
        #pragma unroll
        for (int j = 0; j < 8; j++) acc[j] = 0.f;
        #pragma unroll 4
        for (int cc = 0; cc < CIN_; cc++) {
            float w = rT_Wv[cc * L_ + o];
            const float* xp = &xa[(g * CIN_ + cc) * XAPAD];
            #pragma unroll
            for (int j = 0; j < 8; j++) acc[j] += w * xp[j];
        }
        float* outbuf = &s->lq[0];
        #pragma unroll
        for (int j = 0; j < 8; j++) outbuf[o * LPAD + j] = acc[j];
    }
    __syncthreads();

    // ---- coalesced store: 2 float4 per o-row ----
    {
        const float* outbuf = &s->lq[0];
        for (int t = tid; t < L_ * 2; t += THR) {
            int o = t >> 1, q = t & 1;
            const float* rp = &outbuf[o * LPAD + q * 4];
            float4 v = make_float4(rp[0], rp[1], rp[2], rp[3]);
            *(float4*)&out[((size_t)(b * COUT_ + o)) * N_ + n0 + q * 4] = v;
        }
    }
}

// ---------------- kernel 2: top-16 per (b,g), desc, tie -> lower index ----------------
__global__ __launch_bounds__(256) void k_topk() {
    const int bg  = blockIdx.x;
    const int tid = threadIdx.x;
    __shared__ float v_s[N_];
    __shared__ float rv[256];
    __shared__ int   ri[256];

    for (int i = tid; i < N_; i += 256) v_s[i] = g_cent[bg * N_ + i];
    __syncthreads();

    for (int t = 0; t < K_; t++) {
        float bv = -1e30f; int bi = N_;
        for (int i = tid; i < N_; i += 256) {
            float v = v_s[i];
            if (v > bv || (v == bv && i < bi)) { bv = v; bi = i; }
        }
        rv[tid] = bv; ri[tid] = bi;
        __syncthreads();
        for (int sd = 128; sd > 0; sd >>= 1) {
            if (tid < sd) {
                if (rv[tid + sd] > rv[tid] ||
                    (rv[tid + sd] == rv[tid] && ri[tid + sd] < ri[tid])) {
                    rv[tid] = rv[tid + sd]; ri[tid] = ri[tid + sd];
                }
            }
            __syncthreads();
        }
        if (tid == 0) {
            g_vals[bg * K_ + t] = rv[0];
            g_inds[bg * K_ + t] = ri[0];
            v_s[ri[0]] = -1e30f;
        }
        __syncthreads();
    }
}

// ---------------- kernel 3: non-local prep per (b,g) ----------------
__global__ __launch_bounds__(256) void k_nl_prep(
    const float* __restrict__ abs_x,
    const float* __restrict__ points,
    const float* __restrict__ npe_b1,
    const float* __restrict__ npe_b2)
{
    const int bg = blockIdx.x;
    const int b = bg / G_, g = bg % G_;
    const int tid = threadIdx.x;

    __shared__ int   inds_s[K_];
    __shared__ float rel_s[3][K_];
    __shared__ float h2_s[K_][CNL_];

    if (tid < K_) {
        inds_s[tid] = g_inds[bg * K_ + tid];
        g_tanhvals[bg * K_ + tid] = tanhf(g_vals[bg * K_ + tid]);
    }
    __syncthreads();
    if (tid < 3 * K_) {
        int c = tid / K_, j = tid % K_;
        rel_s[c][j] = tf32r(points[(b * 3 + c) * N_ + inds_s[j]]
                          - points[(b * 3 + c) * N_ + inds_s[0]]);
    }
    __syncthreads();
    {
        int j = tid / CNL_, d = tid % CNL_;
        float h = npe_b1[g * CNL_ + d];
        #pragma unroll
        for (int c = 0; c < 3; c++) h += rel_s[c][j] * r_npe_w1[(g * 3 + c) * CNL_ + d];
        h2_s[j][d] = tf32r(h > 0.f ? h : 0.f);
    }
    __syncthreads();
    {
        int c = tid / K_, j = tid % K_;
        float pe = npe_b2[g * CNL_ + c];
        #pragma unroll
        for (int d = 0; d < CNL_; d++) pe += h2_s[j][d] * r_npe_w2[(g * CNL_ + d) * CNL_ + c];
        int nn = inds_s[j];
        float nk = 0.f, nv2 = 0.f;
        const int row = g * CNL_ + c;
        #pragma unroll 8
        for (int cc = 0; cc < 64; cc++) {
            float a = tf32r(abs_x[(b * 64 + cc) * N_ + nn]);
            nk  += rT_Wnk[cc * NL_ + row]  * a;
            nv2 += rT_Wnv2[cc * NL_ + row] * a;
        }
        g_M[bg * CNL_ * K_ + c * K_ + j]    = nk + pe;
        g_nv2j[bg * CNL_ * K_ + c * K_ + j] = nv2;
    }
}

// ---------------- kernel 4: non-local main (smem-staged, shuffle subgroups) ----------------
struct __align__(16) NLSmem {
    float wnq[64 * 64];
    float wnv1[64 * 64];
    float wnv2[64 * 64];
    float M[G_][CNL_ * K_];
    float nv2jT[G_][K_ * CNL_];
    float tv[G_ * K_];
    float a2[64][4];
    float outbuf[64 * 65];
};

__global__ __launch_bounds__(256) void k_nl_main(
    const float* __restrict__ abs_x,
    float*       __restrict__ out)
{
    extern __shared__ char smraw[];
    NLSmem* s = (NLSmem*)smraw;

    const int blk = blockIdx.x;
    const int b   = blk / (N_ / TNL);
    const int n0  = (blk % (N_ / TNL)) * TNL;
    const int tid = threadIdx.x;
    const int warp  = tid >> 5;
    const int half  = (tid >> 4) & 1;
    const int c     = tid & 15;
    const int g     = (warp & 1) * 2 + half;
    const int nslot = warp >> 1;
    const int o     = g * CNL_ + c;

    for (int i = tid; i < 64 * 64; i += 256) {
        s->wnq[i]  = rT_Wnq[i];
        s->wnv1[i] = rT_Wnv1[i];
        s->wnv2[i] = rT_Wnv2[i];
    }
    for (int i = tid; i < G_ * CNL_ * K_; i += 256) {
        float mv = tf32r(g_M[b * G_ * CNL_ * K_ + i]);
        s->M[0][i] = mv;
        int gg = i >> 8, rem = i & 255, cc2 = rem >> 4, jj = rem & 15;
        s->nv2jT[gg][jj * 16 + cc2] = tf32r(g_nv2j[b * G_ * CNL_ * K_ + i]);
    }
    if (tid < G_ * K_) s->tv[tid] = g_tanhvals[b * G_ * K_ + tid];
    __syncthreads();

    const float tvj = s->tv[g * K_ + c];

    for (int it = 0; it < TNL / 4; it++) {
        const int nb = n0 + it * 4;
        {
            int cc = tid >> 2, nn = tid & 3;
            s->a2[cc][nn] = tf32r(abs_x[(b * 64 + cc) * N_ + nb + nn]);
        }
        __syncthreads();

        float nq = 0.f, nv1 = 0.f, nv2 = 0.f;
        #pragma unroll 8
        for (int cc = 0; cc < 64; cc++) {
            float a = s->a2[cc][nslot];
            nq  += s->wnq[cc * 64 + o]  * a;
            nv1 += s->wnv1[cc * 64 + o] * a;
            nv2 += s->wnv2[cc * 64 + o] * a;
        }
        float nqr = tf32r(nq);

        float sc = 0.f;
        const float* Mg = s->M[g];
        #pragma unroll
        for (int c2 = 0; c2 < CNL_; c2++) {
            float v = __shfl_sync(0xffffffffu, nqr, c2, 16);
            sc += v * Mg[c2 * 16 + c];
        }
        float m = -1e30f;
        #pragma unroll
        for (int j = 0; j < K_; j++) m = fmaxf(m, __shfl_sync(0xffffffffu, sc, j, 16));
        float e = expf(sc - m);
        float sum = 0.f;
        #pragma unroll
        for (int j = 0; j < K_; j++) sum += __shfl_sync(0xffffffffu, e, j, 16);
        float inv = 1.f / sum;
        float w = e * inv * tvj;
        float ws = 0.f;
        #pragma unroll
        for (int j = 0; j < K_; j++) ws += __shfl_sync(0xffffffffu, w, j, 16);

        float og = (nv1 - nv2) * ws;
        const float* nvg = s->nv2jT[g];
        #pragma unroll
        for (int j = 0; j < K_; j++) {
            float wj = tf32r(__shfl_sync(0xffffffffu, w, j, 16));
            og += wj * nvg[j * 16 + c];
        }
        s->outbuf[o * 65 + it * 4 + nslot] = og;
        __syncthreads();
    }

    for (int t = tid; t < 64 * 16; t += 256) {
        int o2 = t >> 4, q = t & 15;
        const float* rp = &s->outbuf[o2 * 65 + q * 4];
        float4 v = make_float4(rp[0], rp[1], rp[2], rp[3]);
        *(float4*)&out[((size_t)(b * COUT_ + L_ + o2)) * N_ + n0 + q * 4] = v;
    }
}

// ---------------- launcher ----------------
extern "C" void kernel_launch(void* const* d_in, const int* in_sizes, int n_in,
                              void* d_out, int out_size) {
    const float* x      = (const float*)d_in[0];
    const float* abs_x  = (const float*)d_in[1];
    const float* points = (const float*)d_in[2];
    const float* Wq     = (const float*)d_in[3];
    const float* Wk     = (const float*)d_in[4];
    const float* Wv     = (const float*)d_in[5];
    const float* Wnq    = (const float*)d_in[6];
    const float* Wnk    = (const float*)d_in[7];
    const float* Wnv1   = (const float*)d_in[8];
    const float* Wnv2   = (const float*)d_in[9];
    const float* pe_w1  = (const float*)d_in[10];
    const float* pe_b1  = (const float*)d_in[11];
    const float* pe_w2  = (const float*)d_in[12];
    const float* pe_b2  = (const float*)d_in[13];
    const float* npe_w1 = (const float*)d_in[14];
    const float* npe_b1 = (const float*)d_in[15];
    const float* npe_w2 = (const float*)d_in[16];
    const float* npe_b2 = (const float*)d_in[17];
    const int*   idx    = (const int*)d_in[18];
    float* out = (float*)d_out;

    static int smem_set = 0;
    if (!smem_set) {
        cudaFuncSetAttribute(k_local, cudaFuncAttributeMaxDynamicSharedMemorySize,
                             (int)sizeof(LocalSmem));
        cudaFuncSetAttribute(k_nl_main, cudaFuncAttributeMaxDynamicSharedMemorySize,
                             (int)sizeof(NLSmem));
        smem_set = 1;
    }

    k_prep<<<128, 256>>>(Wq, Wk, Wv, pe_w1, pe_b1, pe_w2,
                         Wnq, Wnk, Wnv1, Wnv2, npe_w1, npe_w2);
    k_local<<<B_ * (N_ / TN), THR, sizeof(LocalSmem)>>>(x, abs_x, points,
                                                        pe_b2, idx, out);
    k_topk<<<B_ * G_, 256>>>();
    k_nl_prep<<<B_ * G_, 256>>>(abs_x, points, npe_b1, npe_b2);
    k_nl_main<<<B_ * (N_ / TNL), 256, sizeof(NLSmem)>>>(abs_x, out);
}

// round 10
// speedup vs baseline: 12.9242x; 1.0709x over previous
#include <cuda_runtime.h>
#include <math.h>
#include <stdint.h>

#define B_    8
#define CIN_  128
#define N_    2048
#define K_    16
#define G_    4
#define L_    192
#define NL_   64
#define CL_   48
#define CNL_  16
#define COUT_ 256
#define TN    8       // n-tile per CTA in k_local
#define THR   256
#define TNL   64      // n-tile per CTA in k_nl_main

// ---------------- tf32 rounding (emulate cuBLAS TF32 operand conversion) ----------------
__device__ __forceinline__ float tf32r(float a) {
    uint32_t u;
    asm("cvt.rna.tf32.f32 %0, %1;" : "=r"(u) : "f"(a));
    return __uint_as_float(u);
}

// ---------------- scratch (device globals) ----------------
__device__ float g_cent[B_ * G_ * N_];
__device__ float g_vals[B_ * G_ * K_];
__device__ int   g_inds[B_ * G_ * K_];
__device__ float g_M[B_ * G_ * CNL_ * K_];
__device__ float g_nv2j[B_ * G_ * CNL_ * K_];
__device__ float g_tanhvals[B_ * G_ * K_];

// pre-rounded (tf32) weights in access-optimal layouts
__device__ float  rT_Wq[64 * L_];        // [c][o]
__device__ float  r_Wk[L_ * 64];         // [o][cc]
__device__ float  rT_Wv[CIN_ * L_];      // [cc][o]
__device__ float  rT_pe_w2[L_ * L_];     // [c][d]
__device__ float4 g_w1pack[L_];          // {w1x,w1y,w1z,b1}
__device__ float  rT_Wnq[64 * NL_];
__device__ float  rT_Wnk[64 * NL_];
__device__ float  rT_Wnv1[64 * NL_];
__device__ float  rT_Wnv2[64 * NL_];
__device__ float  r_npe_w1[G_ * 3 * CNL_];
__device__ float  r_npe_w2[G_ * CNL_ * CNL_];

// ---------------- kernel: round/transpose weights, zero cent ----------------
__global__ void k_prep(const float* __restrict__ Wq, const float* __restrict__ Wk,
                       const float* __restrict__ Wv,
                       const float* __restrict__ pe_w1, const float* __restrict__ pe_b1,
                       const float* __restrict__ pe_w2,
                       const float* __restrict__ Wnq, const float* __restrict__ Wnk,
                       const float* __restrict__ Wnv1, const float* __restrict__ Wnv2,
                       const float* __restrict__ npe_w1, const float* __restrict__ npe_w2) {
    int tid = blockIdx.x * blockDim.x + threadIdx.x;
    int nth = gridDim.x * blockDim.x;
    for (int i = tid; i < 64 * L_; i += nth) {
        int c = i / L_, o = i % L_;
        rT_Wq[i] = tf32r(Wq[o * 64 + c]);
    }
    for (int i = tid; i < L_ * 64; i += nth) r_Wk[i] = tf32r(Wk[i]);
    for (int i = tid; i < CIN_ * L_; i += nth) {
        int c = i / L_, o = i % L_;
        rT_Wv[i] = tf32r(Wv[o * CIN_ + c]);
    }
    for (int i = tid; i < L_ * L_; i += nth) {
        int c = i / L_, d = i % L_;
        rT_pe_w2[i] = tf32r(pe_w2[d * L_ + c]);
    }
    for (int d = tid; d < L_; d += nth) {
        g_w1pack[d] = make_float4(tf32r(pe_w1[d]), tf32r(pe_w1[L_ + d]),
                                  tf32r(pe_w1[2 * L_ + d]), pe_b1[d]);
    }
    for (int i = tid; i < 64 * NL_; i += nth) {
        int c = i / NL_, o = i % NL_;
        rT_Wnq[i]  = tf32r(Wnq[o * 64 + c]);
        rT_Wnk[i]  = tf32r(Wnk[o * 64 + c]);
        rT_Wnv1[i] = tf32r(Wnv1[o * 64 + c]);
        rT_Wnv2[i] = tf32r(Wnv2[o * 64 + c]);
    }
    for (int i = tid; i < G_ * 3 * CNL_; i += nth)    r_npe_w1[i] = tf32r(npe_w1[i]);
    for (int i = tid; i < G_ * CNL_ * CNL_; i += nth) r_npe_w2[i] = tf32r(npe_w2[i]);
    for (int i = tid; i < B_ * G_ * N_; i += nth) g_cent[i] = 0.f;
}

// ---------------- k_local smem (TN=8) ----------------
#define XROW (TN * K_)       // 128
#define XPAD (XROW + 1)      // 129, conflict-free column access
#define QPAD (TN * G_ + 1)   // 33
#define LPAD 12              // 8 + 4, rows stay 16B aligned (48B stride)
#define XAPAD 12             // xa row pad: 48B, 16B-aligned -> float4 reads in phase G

// NOTE: xa (24576B) overlays qt+kt+lq after phase D1/C1.
// outbuf (9216B) overlays absx..att after phase F.
struct __align__(16) LocalSmem {
    float x[CIN_ * XPAD];        // raw x tile, 66048 B
    float qt[96 * QPAD];         // [dloc][n*4+g], 12672 B
    float kt[64 * QPAD];         // [cc][n*4+g], 8448 B
    float lq[L_ * LPAD];         // [o][n], 9216 B
    float absx[64][TN];          // 2048 B
    float rel[TN][K_][4];        // 2048 B
    float part[2][G_][TN][K_];   // 4096 B
    float att[G_][TN][K_];       // raw att, 2048 B
    float attr[G_][TN][K_];      // tf32-rounded att, 2048 B
    float bconst[G_][TN];        // 256 B
    int   idxs[TN][K_];          // 512 B
};

// ---------------- kernel 1: fused local branch (regrouped, 2 CTA/SM) ----------------
__global__ __launch_bounds__(THR) void k_local(
    const float* __restrict__ x,
    const float* __restrict__ abs_x,
    const float* __restrict__ points,
    const float* __restrict__ pe_b2,
    const int*   __restrict__ idx,
    float*       __restrict__ out)
{
    extern __shared__ char smem_raw[];
    LocalSmem* s = (LocalSmem*)smem_raw;

    const int blk = blockIdx.x;
    const int b   = blk >> 8;              // / 256
    const int n0  = (blk & 255) * TN;
    const int tid = threadIdx.x;

    // ================= phase A: loads =================
    {
        const float* xb = x + ((size_t)(b * CIN_) * N_ + n0) * K_;
        for (int i = tid; i < CIN_ * 32; i += THR) {   // 32 float4 per cc row
            int cc = i >> 5, q = i & 31;
            float4 v = *(const float4*)(xb + (size_t)cc * N_ * K_ + q * 4);
            float* dst = &s->x[cc * XPAD + q * 4];
            dst[0] = v.x; dst[1] = v.y; dst[2] = v.z; dst[3] = v.w;
        }
        for (int i = tid; i < 64 * TN; i += THR) {
            int c = i >> 3, n = i & 7;
            s->absx[c][n] = tf32r(abs_x[(b * 64 + c) * N_ + n0 + n]);
        }
        if (tid < TN * K_) {
            int n = tid >> 4, k = tid & 15;
            s->idxs[n][k] = idx[(b * N_ + n0 + n) * K_ + k];
        }
    }
    __syncthreads();

    // ================= phase B: lq (192 thr) + rel gather (64 thr) =================
    if (tid < 192) {
        const int o = tid;
        float acc[8];
        #pragma unroll
        for (int j = 0; j < 8; j++) acc[j] = 0.f;
        #pragma unroll 8
        for (int c = 0; c < 64; c++) {
            float w = rT_Wq[c * L_ + o];
            const float4* ap = (const float4*)&s->absx[c][0];
            float4 a0 = ap[0], a1 = ap[1];
            acc[0] += w * a0.x; acc[1] += w * a0.y; acc[2] += w * a0.z; acc[3] += w * a0.w;
            acc[4] += w * a1.x; acc[5] += w * a1.y; acc[6] += w * a1.z; acc[7] += w * a1.w;
        }
        #pragma unroll
        for (int j = 0; j < 8; j++) s->lq[o * LPAD + j] = acc[j];
    } else {
        int t = tid - 192;
        for (int r = t; r < 3 * TN * K_; r += 64) {     // 384 elems
            int ax = r >> 7, rem = r & 127, n = rem >> 4, k = rem & 15;
            float p  = points[(b * 3 + ax) * N_ + s->idxs[n][k]];
            float p0 = points[(b * 3 + ax) * N_ + s->idxs[n][0]];
            s->rel[n][k][ax] = tf32r(p - p0);
        }
    }
    __syncthreads();

    // ---- qt task: one thread handles (g, dloc), all 8 n ----
    auto qt_task = [&](int g, int dloc, int dbase) {
        int d = dbase + dloc;
        float acc[8];
        #pragma unroll
        for (int j = 0; j < 8; j++) acc[j] = 0.f;
        const float* wcol = &rT_pe_w2[(g * CL_) * L_ + d];
        #pragma unroll 8
        for (int c = 0; c < CL_; c++) {
            float w = wcol[c * L_];
            const float4* lp = (const float4*)&s->lq[(g * CL_ + c) * LPAD];
            float4 l0 = lp[0], l1 = lp[1];
            acc[0] += w * l0.x; acc[1] += w * l0.y; acc[2] += w * l0.z; acc[3] += w * l0.w;
            acc[4] += w * l1.x; acc[5] += w * l1.y; acc[6] += w * l1.z; acc[7] += w * l1.w;
        }
        #pragma unroll
        for (int j = 0; j < 8; j++)
            s->qt[dloc * QPAD + j * 4 + g] = acc[j];
    };

    // ================= phase C0: qt(d<96) [384 tasks] + kt [256 tasks] =================
    for (int t = tid; t < 640; t += THR) {
        if (t < 384) {
            qt_task(t / 96, t % 96, 0);
        } else {
            int t2 = t - 384;
            int g = t2 >> 6, cc = t2 & 63;
            float acc[8];
            #pragma unroll
            for (int j = 0; j < 8; j++) acc[j] = 0.f;
            #pragma unroll 8
            for (int c = 0; c < CL_; c++) {
                float w = r_Wk[(g * CL_ + c) * 64 + cc];
                const float4* lp = (const float4*)&s->lq[(g * CL_ + c) * LPAD];
                float4 l0 = lp[0], l1 = lp[1];
                acc[0] += w * l0.x; acc[1] += w * l0.y; acc[2] += w * l0.z; acc[3] += w * l0.w;
                acc[4] += w * l1.x; acc[5] += w * l1.y; acc[6] += w * l1.z; acc[7] += w * l1.w;
            }
            #pragma unroll
            for (int j = 0; j < 8; j++) s->kt[cc * QPAD + j * 4 + g] = acc[j];
        }
    }
    __syncthreads();

    auto spe_half = [&](int n, int k, int dstart, int dloc0, float* acc) {
        float rx = s->rel[n][k][0], ry = s->rel[n][k][1], rz = s->rel[n][k][2];
        #pragma unroll 4
        for (int dd = 0; dd < 48; dd++) {
            int d = dstart + dd;
            float4 wp = g_w1pack[d];
            float hv = rx * wp.x + ry * wp.y + rz * wp.z + wp.w;
            hv = hv > 0.f ? hv : 0.f;
            hv = tf32r(hv);
            const float* qp = &s->qt[(dloc0 + dd) * QPAD + n * 4];
            acc[0] += qp[0] * hv; acc[1] += qp[1] * hv;
            acc[2] += qp[2] * hv; acc[3] += qp[3] * hv;
        }
    };

    // ================= phase D0: S_pe(d<96) + S_k  (256 = 2dq x 8n x 16k) =================
    {
        int dq = tid >> 7, r = tid & 127, n = r >> 4, k = r & 15;
        float acc[4] = {0.f, 0.f, 0.f, 0.f};
        spe_half(n, k, dq * 48, dq * 48, acc);
        #pragma unroll 4
        for (int cc = dq * 32; cc < dq * 32 + 32; cc++) {
            float lo = s->x[cc * XPAD + n * 16 + k];
            float hi = s->x[(cc + 64) * XPAD + n * 16 + k];
            float xsv = tf32r(lo + hi);
            const float* kp = &s->kt[cc * QPAD + n * 4];
            acc[0] += kp[0] * xsv; acc[1] += kp[1] * xsv;
            acc[2] += kp[2] * xsv; acc[3] += kp[3] * xsv;
        }
        #pragma unroll
        for (int g = 0; g < 4; g++) s->part[dq][g][n][k] = acc[g];
    }
    __syncthreads();

    // ================= phase C1: qt(d>=96) [384] + bconst [32] =================
    for (int t = tid; t < 416; t += THR) {
        if (t < 384) {
            qt_task(t / 96, t % 96, 96);
        } else {
            int t2 = t - 384;
            int g = t2 >> 3, n = t2 & 7;
            float sum = 0.f;
            #pragma unroll 8
            for (int c = 0; c < CL_; c++)
                sum += s->lq[(g * CL_ + c) * LPAD + n] * pe_b2[g * CL_ + c];
            s->bconst[g][n] = sum;
        }
    }
    __syncthreads();

    // ================= phase D1: S_pe(d>=96), accumulate =================
    {
        int dq = tid >> 7, r = tid & 127, n = r >> 4, k = r & 15;
        float acc[4] = {0.f, 0.f, 0.f, 0.f};
        spe_half(n, k, 96 + dq * 48, dq * 48, acc);
        #pragma unroll
        for (int g = 0; g < 4; g++) s->part[dq][g][n][k] += acc[g];
    }
    __syncthreads();

    // ================= phase E: combine + softmax (32 tasks) =================
    if (tid < G_ * TN) {
        int g = tid >> 3, n = tid & 7;
        float sc[K_];
        float m = -1e30f;
        #pragma unroll
        for (int k = 0; k < K_; k++) {
            sc[k] = s->part[0][g][n][k] + s->part[1][g][n][k] + s->bconst[g][n];
            m = fmaxf(m, sc[k]);
        }
        float sum = 0.f;
        #pragma unroll
        for (int k = 0; k < K_; k++) { sc[k] = expf(sc[k] - m); sum += sc[k]; }
        float inv = 1.f / sum;
        #pragma unroll
        for (int k = 0; k < K_; k++) {
            float a = sc[k] * inv;
            s->att[g][n][k]  = a;
            s->attr[g][n][k] = tf32r(a);
        }
    }
    __syncthreads();

    // ================= phase F: scatter + xa =================
    {
        for (int t = tid; t < G_ * TN * K_; t += THR) {   // 512 atomics
            int g = t >> 7, rem = t & 127, n = rem >> 4, k = rem & 15;
            atomicAdd(&g_cent[(b * G_ + g) * N_ + s->idxs[n][k]], s->att[g][n][k]);
        }
        float* xa = &s->qt[0];   // overlays qt+kt+lq (30336B >= 512*12*4=24576B)
        int cc = tid & 127, nset = tid >> 7;              // nset 0..1
        for (int ni = 0; ni < 4; ni++) {
            int n = nset * 4 + ni;
            float acc[4] = {0.f, 0.f, 0.f, 0.f};
            #pragma unroll
            for (int k = 0; k < K_; k++) {
                float xv = tf32r(s->x[cc * XPAD + n * 16 + k]);
                acc[0] += s->attr[0][n][k] * xv;
                acc[1] += s->attr[1][n][k] * xv;
                acc[2] += s->attr[2][n][k] * xv;
                acc[3] += s->attr[3][n][k] * xv;
            }
            #pragma unroll
            for (int g = 0; g < 4; g++) xa[(g * CIN_ + cc) * XAPAD + n] = acc[g];
        }
    }
    __syncthreads();

    // ================= phase G: out = Wv^T-dot(xa) (192 thr) =================
    if (tid < 192) {
        const float* xa = &s->qt[0];
        int o = tid;
        int g = o / CL_;
        float acc[8];
        #pragma unroll
        for (int j = 0; j < 8; j++) acc[j] = 0.f;
        #pragma unroll 8
        for (int cc = 0; cc < CIN_; cc++) {
            float w = rT_Wv[cc * L_ + o];
            const float4* xp = (const float4*)&xa[(g * CIN_ + cc) * XAPAD];
            float4 x0 = xp[0], x1 = xp[1];
            acc[0] += w * x0.x; acc[1] += w * x0.y; acc[2] += w * x0.z; acc[3] += w * x0.w;
            acc[4] += w * x1.x; acc[5] += w * x1.y; acc[6] += w * x1.z; acc[7] += w * x1.w;
        }
        float* outbuf = &s->absx[0][0];   // overlays absx..att (10240B >= 192*12*4=9216B)
        float4* orow = (float4*)&outbuf[o * LPAD];
        orow[0] = make_float4(acc[0], acc[1], acc[2], acc[3]);
        orow[1] = make_float4(acc[4], acc[5], acc[6], acc[7]);
    }
    __syncthreads();

    // ---- coalesced store: 2 float4 per o-row ----
    {
        const float* outbuf = &s->absx[0][0];
        for (int t = tid; t < L_ * 2; t += THR) {
            int o = t >> 1, q = t & 1;
            const float* rp = &outbuf[o * LPAD + q * 4];
            float4 v = make_float4(rp[0], rp[1], rp[2], rp[3]);
            *(float4*)&out[((size_t)(b * COUT_ + o)) * N_ + n0 + q * 4] = v;
        }
    }
}

// ---------------- kernel 2: top-16 per (b,g), desc, tie -> lower index ----------------
__global__ __launch_bounds__(256) void k_topk() {
    const int bg  = blockIdx.x;
    const int tid = threadIdx.x;
    __shared__ float v_s[N_];
    __shared__ float rv[256];
    __shared__ int   ri[256];

    for (int i = tid; i < N_; i += 256) v_s[i] = g_cent[bg * N_ + i];
    __syncthreads();

    for (int t = 0; t < K_; t++) {
        float bv = -1e30f; int bi = N_;
        for (int i = tid; i < N_; i += 256) {
            float v = v_s[i];
            if (v > bv || (v == bv && i < bi)) { bv = v; bi = i; }
        }
        rv[tid] = bv; ri[tid] = bi;
        __syncthreads();
        for (int sd = 128; sd > 0; sd >>= 1) {
            if (tid < sd) {
                if (rv[tid + sd] > rv[tid] ||
                    (rv[tid + sd] == rv[tid] && ri[tid + sd] < ri[tid])) {
                    rv[tid] = rv[tid + sd]; ri[tid] = ri[tid + sd];
                }
            }
            __syncthreads();
        }
        if (tid == 0) {
            g_vals[bg * K_ + t] = rv[0];
            g_inds[bg * K_ + t] = ri[0];
            v_s[ri[0]] = -1e30f;
        }
        __syncthreads();
    }
}

// ---------------- kernel 3: non-local prep per (b,g) ----------------
__global__ __launch_bounds__(256) void k_nl_prep(
    const float* __restrict__ abs_x,
    const float* __restrict__ points,
    const float* __restrict__ npe_b1,
    const float* __restrict__ npe_b2)
{
    const int bg = blockIdx.x;
    const int b = bg / G_, g = bg % G_;
    const int tid = threadIdx.x;

    __shared__ int   inds_s[K_];
    __shared__ float rel_s[3][K_];
    __shared__ float h2_s[K_][CNL_];

    if (tid < K_) {
        inds_s[tid] = g_inds[bg * K_ + tid];
        g_tanhvals[bg * K_ + tid] = tanhf(g_vals[bg * K_ + tid]);
    }
    __syncthreads();
    if (tid < 3 * K_) {
        int c = tid / K_, j = tid % K_;
        rel_s[c][j] = tf32r(points[(b * 3 + c) * N_ + inds_s[j]]
                          - points[(b * 3 + c) * N_ + inds_s[0]]);
    }
    __syncthreads();
    {
        int j = tid / CNL_, d = tid % CNL_;
        float h = npe_b1[g * CNL_ + d];
        #pragma unroll
        for (int c = 0; c < 3; c++) h += rel_s[c][j] * r_npe_w1[(g * 3 + c) * CNL_ + d];
        h2_s[j][d] = tf32r(h > 0.f ? h : 0.f);
    }
    __syncthreads();
    {
        int c = tid / K_, j = tid % K_;
        float pe = npe_b2[g * CNL_ + c];
        #pragma unroll
        for (int d = 0; d < CNL_; d++) pe += h2_s[j][d] * r_npe_w2[(g * CNL_ + d) * CNL_ + c];
        int nn = inds_s[j];
        float nk = 0.f, nv2 = 0.f;
        const int row = g * CNL_ + c;
        #pragma unroll 8
        for (int cc = 0; cc < 64; cc++) {
            float a = tf32r(abs_x[(b * 64 + cc) * N_ + nn]);
            nk  += rT_Wnk[cc * NL_ + row]  * a;
            nv2 += rT_Wnv2[cc * NL_ + row] * a;
        }
        g_M[bg * CNL_ * K_ + c * K_ + j]    = nk + pe;
        g_nv2j[bg * CNL_ * K_ + c * K_ + j] = nv2;
    }
}

// ---------------- kernel 4: non-local main (smem-staged, shuffle subgroups) ----------------
struct __align__(16) NLSmem {
    float wnq[64 * 64];
    float wnv1[64 * 64];
    float wnv2[64 * 64];
    float M[G_][CNL_ * K_];
    float nv2jT[G_][K_ * CNL_];
    float tv[G_ * K_];
    float a2[64][4];
    float outbuf[64 * 65];
};

__global__ __launch_bounds__(256) void k_nl_main(
    const float* __restrict__ abs_x,
    float*       __restrict__ out)
{
    extern __shared__ char smraw[];
    NLSmem* s = (NLSmem*)smraw;

    const int blk = blockIdx.x;
    const int b   = blk / (N_ / TNL);
    const int n0  = (blk % (N_ / TNL)) * TNL;
    const int tid = threadIdx.x;
    const int warp  = tid >> 5;
    const int half  = (tid >> 4) & 1;
    const int c     = tid & 15;
    const int g     = (warp & 1) * 2 + half;
    const int nslot = warp >> 1;
    const int o     = g * CNL_ + c;

    for (int i = tid; i < 64 * 64; i += 256) {
        s->wnq[i]  = rT_Wnq[i];
        s->wnv1[i] = rT_Wnv1[i];
        s->wnv2[i] = rT_Wnv2[i];
    }
    for (int i = tid; i < G_ * CNL_ * K_; i += 256) {
        float mv = tf32r(g_M[b * G_ * CNL_ * K_ + i]);
        s->M[0][i] = mv;
        int gg = i >> 8, rem = i & 255, cc2 = rem >> 4, jj = rem & 15;
        s->nv2jT[gg][jj * 16 + cc2] = tf32r(g_nv2j[b * G_ * CNL_ * K_ + i]);
    }
    if (tid < G_ * K_) s->tv[tid] = g_tanhvals[b * G_ * K_ + tid];
    __syncthreads();

    const float tvj = s->tv[g * K_ + c];

    for (int it = 0; it < TNL / 4; it++) {
        const int nb = n0 + it * 4;
        {
            int cc = tid >> 2, nn = tid & 3;
            s->a2[cc][nn] = tf32r(abs_x[(b * 64 + cc) * N_ + nb + nn]);
        }
        __syncthreads();

        float nq = 0.f, nv1 = 0.f, nv2 = 0.f;
        #pragma unroll 8
        for (int cc = 0; cc < 64; cc++) {
            float a = s->a2[cc][nslot];
            nq  += s->wnq[cc * 64 + o]  * a;
            nv1 += s->wnv1[cc * 64 + o] * a;
            nv2 += s->wnv2[cc * 64 + o] * a;
        }
        float nqr = tf32r(nq);

        float sc = 0.f;
        const float* Mg = s->M[g];
        #pragma unroll
        for (int c2 = 0; c2 < CNL_; c2++) {
            float v = __shfl_sync(0xffffffffu, nqr, c2, 16);
            sc += v * Mg[c2 * 16 + c];
        }
        float m = -1e30f;
        #pragma unroll
        for (int j = 0; j < K_; j++) m = fmaxf(m, __shfl_sync(0xffffffffu, sc, j, 16));
        float e = expf(sc - m);
        float sum = 0.f;
        #pragma unroll
        for (int j = 0; j < K_; j++) sum += __shfl_sync(0xffffffffu, e, j, 16);
        float inv = 1.f / sum;
        float w = e * inv * tvj;
        float ws = 0.f;
        #pragma unroll
        for (int j = 0; j < K_; j++) ws += __shfl_sync(0xffffffffu, w, j, 16);

        float og = (nv1 - nv2) * ws;
        const float* nvg = s->nv2jT[g];
        #pragma unroll
        for (int j = 0; j < K_; j++) {
            float wj = tf32r(__shfl_sync(0xffffffffu, w, j, 16));
            og += wj * nvg[j * 16 + c];
        }
        s->outbuf[o * 65 + it * 4 + nslot] = og;
        __syncthreads();
    }

    for (int t = tid; t < 64 * 16; t += 256) {
        int o2 = t >> 4, q = t & 15;
        const float* rp = &s->outbuf[o2 * 65 + q * 4];
        float4 v = make_float4(rp[0], rp[1], rp[2], rp[3]);
        *(float4*)&out[((size_t)(b * COUT_ + L_ + o2)) * N_ + n0 + q * 4] = v;
    }
}

// ---------------- launcher ----------------
extern "C" void kernel_launch(void* const* d_in, const int* in_sizes, int n_in,
                              void* d_out, int out_size) {
    const float* x      = (const float*)d_in[0];
    const float* abs_x  = (const float*)d_in[1];
    const float* points = (const float*)d_in[2];
    const float* Wq     = (const float*)d_in[3];
    const float* Wk     = (const float*)d_in[4];
    const float* Wv     = (const float*)d_in[5];
    const float* Wnq    = (const float*)d_in[6];
    const float* Wnk    = (const float*)d_in[7];
    const float* Wnv1   = (const float*)d_in[8];
    const float* Wnv2   = (const float*)d_in[9];
    const float* pe_w1  = (const float*)d_in[10];
    const float* pe_b1  = (const float*)d_in[11];
    const float* pe_w2  = (const float*)d_in[12];
    const float* pe_b2  = (const float*)d_in[13];
    const float* npe_w1 = (const float*)d_in[14];
    const float* npe_b1 = (const float*)d_in[15];
    const float* npe_w2 = (const float*)d_in[16];
    const float* npe_b2 = (const float*)d_in[17];
    const int*   idx    = (const int*)d_in[18];
    float* out = (float*)d_out;

    static int smem_set = 0;
    if (!smem_set) {
        cudaFuncSetAttribute(k_local, cudaFuncAttributeMaxDynamicSharedMemorySize,
                             (int)sizeof(LocalSmem));
        cudaFuncSetAttribute(k_nl_main, cudaFuncAttributeMaxDynamicSharedMemorySize,
                             (int)sizeof(NLSmem));
        smem_set = 1;
    }

    k_prep<<<128, 256>>>(Wq, Wk, Wv, pe_w1, pe_b1, pe_w2,
                         Wnq, Wnk, Wnv1, Wnv2, npe_w1, npe_w2);
    k_local<<<B_ * (N_ / TN), THR, sizeof(LocalSmem)>>>(x, abs_x, points,
                                                        pe_b2, idx, out);
    k_topk<<<B_ * G_, 256>>>();
    k_nl_prep<<<B_ * G_, 256>>>(abs_x, points, npe_b1, npe_b2);
    k_nl_main<<<B_ * (N_ / TNL), 256, sizeof(NLSmem)>>>(abs_x, out);
}